// round 12
// baseline (speedup 1.0000x reference)
#include <cuda_runtime.h>
#include <cuda_bf16.h>
#include <cstdint>

#define DM 2048
#define NH 16
#define DH 128
#define BB 2
#define SS 2048
#define MT (BB*SS)   // 4096 rows

// ---------------------------------------------------------------------------
// Device scratch (allocation-free per harness rules)
// ---------------------------------------------------------------------------
__device__ float g_Q[(size_t)MT*DM];                 // fp32 (fallback path only)
__device__ float g_K[(size_t)MT*DM];
__device__ float g_V[(size_t)MT*DM];
__device__ float g_maskT[(size_t)SS*SS];             // mask^T * log2e
__device__ __nv_bfloat16 g_Qh[(size_t)MT*DM];        // [B,H,S,d] splits (a-path)
__device__ __nv_bfloat16 g_Ql[(size_t)MT*DM];
__device__ __nv_bfloat16 g_Kh[(size_t)MT*DM];
__device__ __nv_bfloat16 g_Kl[(size_t)MT*DM];
__device__ __nv_bfloat16 g_Vth[(size_t)MT*DM];       // V^T [B,H,d,S]
__device__ __nv_bfloat16 g_Vtl[(size_t)MT*DM];
__device__ __nv_bfloat16 g_Xh[(size_t)MT*DM];        // x split  [M,K]
__device__ __nv_bfloat16 g_Xl[(size_t)MT*DM];
__device__ __nv_bfloat16 g_Ch[(size_t)MT*DM];        // attention ctx split [M,K]
__device__ __nv_bfloat16 g_Cl[(size_t)MT*DM];
__device__ __nv_bfloat16 g_Wh[(size_t)4*DM*DM];      // transposed weights [N,K], z: q,k,v,o
__device__ __nv_bfloat16 g_Wl[(size_t)4*DM*DM];

// ---------------------------------------------------------------------------
// tcgen05 helpers — only in the sm_103a feature pass; plain sm_103 pass gets
// SIMT fallback bodies so both ptxas passes compile.
// ---------------------------------------------------------------------------
__device__ __forceinline__ uint32_t smem_u32(const void* p) {
    uint32_t a;
    asm("{ .reg .u64 t; cvta.to.shared.u64 t, %1; cvt.u32.u64 %0, t; }" : "=r"(a) : "l"(p));
    return a;
}

#if defined(__CUDA_ARCH_FEAT_SM103_ALL)

#define TC_ALLOC(sm, n)  asm volatile("tcgen05.alloc.cta_group::1.sync.aligned.shared::cta.b32 [%0], %1;" :: "r"(sm), "r"(n) : "memory")
#define TC_RELINQ()      asm volatile("tcgen05.relinquish_alloc_permit.cta_group::1.sync.aligned;")
#define TC_DEALLOC(t, n) asm volatile("tcgen05.dealloc.cta_group::1.sync.aligned.b32 %0, %1;" :: "r"(t), "r"(n))
#define TC_COMMIT(mb)    asm volatile("tcgen05.commit.cta_group::1.mbarrier::arrive::one.shared::cluster.b64 [%0];" :: "r"(mb) : "memory")
#define TC_FENCE_AFTER() asm volatile("tcgen05.fence::after_thread_sync;" ::: "memory")
#define TC_WAIT_LD()     asm volatile("tcgen05.wait::ld.sync.aligned;" ::: "memory")
#define MBAR_INIT(mb, c) asm volatile("mbarrier.init.shared.b64 [%0], %1;" :: "r"(mb), "r"(c) : "memory")
#define FENCE_ASYNC()    asm volatile("fence.proxy.async.shared::cta;" ::: "memory")

#define MBAR_WAIT(mb, ph) do {                                                   \
    uint32_t _m = (mb), _p = (ph), _d;                                           \
    asm volatile("{\n\t.reg .pred p;\n\t"                                        \
        "mbarrier.try_wait.parity.acquire.cta.shared::cta.b64 p, [%1], %2;\n\t"  \
        "selp.b32 %0, 1, 0, p;\n\t}"                                             \
        : "=r"(_d) : "r"(_m), "r"(_p) : "memory");                               \
    if (!_d) {                                                                   \
        asm volatile("{\n\t.reg .pred P1;\n\t"                                   \
        "WL_%=:\n\t"                                                             \
        "mbarrier.try_wait.parity.acquire.cta.shared::cta.b64 P1, [%0], %1, 0x989680;\n\t" \
        "@P1 bra.uni WD_%=;\n\t"                                                 \
        "bra.uni WL_%=;\n\t"                                                     \
        "WD_%=:\n\t}" :: "r"(_m), "r"(_p) : "memory");                           \
    }                                                                            \
} while (0)

#define TC_LD_X32(r, ta)                                                         \
    asm volatile("tcgen05.ld.sync.aligned.32x32b.x32.b32 "                       \
        "{%0, %1, %2, %3, %4, %5, %6, %7, "                                      \
        " %8, %9, %10, %11, %12, %13, %14, %15, "                                \
        " %16, %17, %18, %19, %20, %21, %22, %23, "                              \
        " %24, %25, %26, %27, %28, %29, %30, %31}, [%32];"                       \
        : "=r"((r)[0]), "=r"((r)[1]), "=r"((r)[2]), "=r"((r)[3]),                \
          "=r"((r)[4]), "=r"((r)[5]), "=r"((r)[6]), "=r"((r)[7]),                \
          "=r"((r)[8]), "=r"((r)[9]), "=r"((r)[10]), "=r"((r)[11]),              \
          "=r"((r)[12]), "=r"((r)[13]), "=r"((r)[14]), "=r"((r)[15]),            \
          "=r"((r)[16]), "=r"((r)[17]), "=r"((r)[18]), "=r"((r)[19]),            \
          "=r"((r)[20]), "=r"((r)[21]), "=r"((r)[22]), "=r"((r)[23]),            \
          "=r"((r)[24]), "=r"((r)[25]), "=r"((r)[26]), "=r"((r)[27]),            \
          "=r"((r)[28]), "=r"((r)[29]), "=r"((r)[30]), "=r"((r)[31])             \
        : "r"(ta))

// SW128 K-major SMEM descriptor (layout=2, version=1, SBO=64, LBO=1)
static __device__ __forceinline__ uint64_t make_desc(uint32_t addr) {
    const uint64_t base =
        (uint64_t(2) << 61) | (uint64_t(1) << 46) | (uint64_t(64) << 32) | (uint64_t(1) << 16);
    return base | ((uint64_t)(addr >> 4) & 0x3FFF);
}

// idesc: dtype=F32, atype=btype=BF16, M=128, N variable
#define IDESC_N128 ((1u<<4) | (1u<<7) | (1u<<10) | ((128u/8)<<17) | ((128u/16)<<24))
#define IDESC_N64  ((1u<<4) | (1u<<7) | (1u<<10) | ((64u/8)<<17)  | ((128u/16)<<24))

__device__ __forceinline__ void mma_f16_ss(uint32_t d, uint64_t a, uint64_t b,
                                           uint32_t idesc, uint32_t en) {
    asm volatile(
        "{\n\t.reg .pred p;\n\t"
        "setp.ne.u32 p, %4, 0;\n\t"
        "tcgen05.mma.cta_group::1.kind::f16 [%0], %1, %2, %3, {%5,%5,%5,%5}, p;\n\t}"
        :: "r"(d), "l"(a), "l"(b), "r"(idesc), "r"(en), "r"(0u) : "memory");
}

#endif  // __CUDA_ARCH_FEAT_SM103_ALL

// ---------------------------------------------------------------------------
// Prep 1: split x into bf16 hi/lo
// ---------------------------------------------------------------------------
__global__ void split_x_kernel(const float* __restrict__ x)
{
    size_t i = ((size_t)blockIdx.x * 256 + threadIdx.x) * 4;
    float4 v = *(const float4*)(x + i);
    __nv_bfloat16 h[4], l[4];
    float vv[4] = {v.x, v.y, v.z, v.w};
#pragma unroll
    for (int j = 0; j < 4; j++) {
        h[j] = __float2bfloat16(vv[j]);
        l[j] = __float2bfloat16(vv[j] - __bfloat162float(h[j]));
    }
    *(uint2*)&g_Xh[i] = *(uint2*)h;
    *(uint2*)&g_Xl[i] = *(uint2*)l;
}

// ---------------------------------------------------------------------------
// Prep 2: transpose + split weights. W[K,N] fp32 -> Wt[N,K] bf16 hi/lo.
// ---------------------------------------------------------------------------
__global__ void wsplit_kernel(const float* __restrict__ wq, const float* __restrict__ wk,
                              const float* __restrict__ wv, const float* __restrict__ wo)
{
    __shared__ float t[32][33];
    const int z = blockIdx.z;
    const float* __restrict__ W = (z == 0) ? wq : (z == 1) ? wk : (z == 2) ? wv : wo;
    const int n0 = blockIdx.x << 5;
    const int k0 = blockIdx.y << 5;
    const int tx = threadIdx.x & 31;
    const int ty = threadIdx.x >> 5;   // 0..7

#pragma unroll
    for (int r = ty; r < 32; r += 8)
        t[r][tx] = W[(size_t)(k0 + r) * DM + n0 + tx];
    __syncthreads();

    const size_t zoff = (size_t)z * DM * DM;
#pragma unroll
    for (int r = ty; r < 32; r += 8) {
        float v = t[tx][r];    // = W[k0+tx][n0+r]
        __nv_bfloat16 h = __float2bfloat16(v);
        float lo = v - __bfloat162float(h);
        size_t o = zoff + (size_t)(n0 + r) * DM + k0 + tx;
        g_Wh[o] = h;
        g_Wl[o] = __float2bfloat16(lo);
    }
}

// ---------------------------------------------------------------------------
// Prep 3: maskT[kv][q] = mask[q][kv] * log2e.
// ---------------------------------------------------------------------------
__global__ void mtrans_kernel(const float* __restrict__ mask)
{
    __shared__ float t[32][33];
    const int x0 = blockIdx.x << 5;     // kv tile
    const int y0 = blockIdx.y << 5;     // q tile
    const int tx = threadIdx.x & 31;
    const int ty = threadIdx.x >> 5;    // 0..7

#pragma unroll
    for (int r = ty; r < 32; r += 8)
        t[r][tx] = mask[(size_t)(y0 + r) * SS + x0 + tx];
    __syncthreads();
#pragma unroll
    for (int r = ty; r < 32; r += 8)
        g_maskT[(size_t)(x0 + r) * SS + y0 + tx] =
            t[tx][r] * 1.4426950408889634f;
}

// ---------------------------------------------------------------------------
// GEMM: D[128,128] = A[128,K] @ Wt[N,K]^T (+bias), bf16 2-split.
// a-path: DOUBLE-BUFFERED SMEM (2x64KB) + register prefetch. STS(t) waits only
// on MMA(t-2) (same buffer); MMA(t) is issued without waiting for MMA(t-1) —
// the tcgen05 queue serializes in-order, so the loop is MMA-paced.
// ---------------------------------------------------------------------------
#define GK 64
#define SM_MB0  8
#define SM_MB1  16
#define SM_A    1024
#define SM_TILE 16384                     // 128*64*2B
#define SM_BUF  (4*SM_TILE)               // one buffer set: Ah,Al,Bh,Bl
#define GEMM_SMEM (1024 + 2*SM_BUF)       // 132 KB

__global__ __launch_bounds__(256, 1) void tc_gemm(
    const float* __restrict__ b0, const float* __restrict__ b1, const float* __restrict__ b2,
    float* __restrict__ outp, int wsel, int split)
{
    extern __shared__ char smem[];
    const int tid = threadIdx.x;
    const int z   = blockIdx.z;
    const int m0  = blockIdx.y << 7;
    const int n0  = blockIdx.x << 7;

    const __nv_bfloat16* __restrict__ Ah = (split ? g_Xh : g_Ch) + (size_t)m0 * DM;
    const __nv_bfloat16* __restrict__ Al = (split ? g_Xl : g_Cl) + (size_t)m0 * DM;
    const size_t wz = (size_t)(wsel + z) * DM * DM;
    const __nv_bfloat16* __restrict__ Bh = g_Wh + wz + (size_t)n0 * DM;
    const __nv_bfloat16* __restrict__ Bl = g_Wl + wz + (size_t)n0 * DM;
    const float* __restrict__ bias = (z == 0) ? b0 : (z == 1) ? b1 : b2;

#if defined(__CUDA_ARCH_FEAT_SM103_ALL)
    // ------------------------- tcgen05 path -------------------------
    const uint32_t sb = smem_u32(smem);
    const int wid = tid >> 5;

    if (wid == 0) {
        TC_ALLOC(sb, 128);
        TC_RELINQ();
    }
    if (tid == 0) { MBAR_INIT(sb + SM_MB0, 1); MBAR_INIT(sb + SM_MB1, 1); }

    // per-thread tile addresses (4 chunks)
    uint32_t tsw[4]; size_t tgo[4];
#pragma unroll
    for (int it = 0; it < 4; it++) {
        int idx = tid + it * 256;          // 0..1023
        int row = idx >> 3;                // 0..127
        int cc  = idx & 7;                 // 16B chunk
        uint32_t off = row * 128 + cc * 16;
        tsw[it] = off ^ ((off >> 3) & 0x70);
        tgo[it] = (size_t)row * DM + cc * 8;   // + k0
    }

    __syncthreads();
    uint32_t tmem;
    asm volatile("ld.shared.b32 %0, [%1];" : "=r"(tmem) : "r"(sb));

    uint64_t dA[2][2], dB[2][2];           // [buf][hi/lo]
#pragma unroll
    for (int bf = 0; bf < 2; bf++) {
        uint32_t base = sb + SM_A + bf * SM_BUF;
        dA[bf][0] = make_desc(base);
        dA[bf][1] = make_desc(base + SM_TILE);
        dB[bf][0] = make_desc(base + 2 * SM_TILE);
        dB[bf][1] = make_desc(base + 3 * SM_TILE);
    }

    const int NIT = DM / GK;               // 32
    for (int t = 0; t < NIT; t++) {
        const int bf = t & 1;
        char* bufp = smem + SM_A + bf * SM_BUF;
        const size_t k0 = (size_t)t * GK;

        // prefetch into registers (overlaps in-flight MMAs)
        uint4 rah[4], ral[4], rbh[4], rbl[4];
#pragma unroll
        for (int it = 0; it < 4; it++) {
            size_t g = tgo[it] + k0;
            rah[it] = *(const uint4*)(Ah + g);
            ral[it] = *(const uint4*)(Al + g);
            rbh[it] = *(const uint4*)(Bh + g);
            rbl[it] = *(const uint4*)(Bl + g);
        }

        // wait for MMA(t-2) (same buffer) before overwriting
        if (t >= 2) MBAR_WAIT(sb + (bf ? SM_MB1 : SM_MB0), ((t >> 1) - 1) & 1);

#pragma unroll
        for (int it = 0; it < 4; it++) {
            *(uint4*)(bufp + tsw[it])               = rah[it];
            *(uint4*)(bufp + SM_TILE + tsw[it])     = ral[it];
            *(uint4*)(bufp + 2 * SM_TILE + tsw[it]) = rbh[it];
            *(uint4*)(bufp + 3 * SM_TILE + tsw[it]) = rbl[it];
        }
        __syncthreads();
        if (tid == 0) {
            FENCE_ASYNC();
#pragma unroll
            for (int s = 0; s < 4; s++) {
                uint64_t oa = (uint64_t)(s * 2);
                mma_f16_ss(tmem, dA[bf][0] + oa, dB[bf][0] + oa, IDESC_N128, !(t == 0 && s == 0));
                mma_f16_ss(tmem, dA[bf][0] + oa, dB[bf][1] + oa, IDESC_N128, 1u);
                mma_f16_ss(tmem, dA[bf][1] + oa, dB[bf][0] + oa, IDESC_N128, 1u);
            }
            TC_COMMIT(sb + (bf ? SM_MB1 : SM_MB0));
        }
    }
    // drain: last commits on each mbar (16 commits each -> parity 1)
    MBAR_WAIT(sb + SM_MB0, ((NIT / 2) - 1) & 1);
    MBAR_WAIT(sb + SM_MB1, ((NIT / 2) - 1) & 1);
    TC_FENCE_AFTER();

    if (wid < 4) {
        const int lid = tid & 31;
        const int m = m0 + wid * 32 + lid;
        const int bb = m >> 11;
        const int s  = m & (SS - 1);
        const int h  = n0 >> 7;
#pragma unroll
        for (int cc = 0; cc < 4; cc++) {
            uint32_t dr[32];
            TC_LD_X32(dr, tmem + cc * 32);
            TC_WAIT_LD();
            int coff = cc * 32;
            if (!split) {
                size_t base = (size_t)m * DM + n0 + coff;
#pragma unroll
                for (int j = 0; j < 32; j += 4) {
                    float4 r;
                    r.x = __uint_as_float(dr[j + 0]) + bias[n0 + coff + j + 0];
                    r.y = __uint_as_float(dr[j + 1]) + bias[n0 + coff + j + 1];
                    r.z = __uint_as_float(dr[j + 2]) + bias[n0 + coff + j + 2];
                    r.w = __uint_as_float(dr[j + 3]) + bias[n0 + coff + j + 3];
                    *(float4*)(outp + base + j) = r;
                }
            } else if (z == 2) {
                // V^T: [B,H][d][S], d = coff+j
                size_t vbase = (size_t)(bb * NH + h) * DH * SS + s;
#pragma unroll
                for (int j = 0; j < 32; j++) {
                    float v = __uint_as_float(dr[j]) + bias[n0 + coff + j];
                    __nv_bfloat16 hh = __float2bfloat16(v);
                    size_t o = vbase + (size_t)(coff + j) * SS;
                    g_Vth[o] = hh;
                    g_Vtl[o] = __float2bfloat16(v - __bfloat162float(hh));
                }
            } else {
                // Q/K: [B,H,S,d] bf16 splits, pair stores
                __nv_bfloat16* __restrict__ oh = (z == 0) ? g_Qh : g_Kh;
                __nv_bfloat16* __restrict__ ol = (z == 0) ? g_Ql : g_Kl;
                size_t base = ((size_t)(bb * NH + h) * SS + s) * DH + coff;
#pragma unroll
                for (int j = 0; j < 32; j += 2) {
                    float v0 = __uint_as_float(dr[j])     + bias[n0 + coff + j];
                    float v1 = __uint_as_float(dr[j + 1]) + bias[n0 + coff + j + 1];
                    __nv_bfloat16 h0 = __float2bfloat16(v0);
                    __nv_bfloat16 h1 = __float2bfloat16(v1);
                    __nv_bfloat16 l0 = __float2bfloat16(v0 - __bfloat162float(h0));
                    __nv_bfloat16 l1 = __float2bfloat16(v1 - __bfloat162float(h1));
                    __nv_bfloat16 hp[2] = {h0, h1}, lp[2] = {l0, l1};
                    *(uint32_t*)(oh + base + j) = *(uint32_t*)hp;
                    *(uint32_t*)(ol + base + j) = *(uint32_t*)lp;
                }
            }
        }
    }
    __syncthreads();
    if (wid == 0) TC_DEALLOC(tmem, 128);

#else
    // ------------------------- SIMT fallback (sm_103 pass) -------------------------
    float* As = (float*)smem;            // [16][132]
    float* Bs = As + 16 * 132;           // [16][128]
    const int ty = tid >> 4;
    const int tx = tid & 15;

    float acc[8][8];
#pragma unroll
    for (int i = 0; i < 8; i++)
#pragma unroll
        for (int j = 0; j < 8; j++) acc[i][j] = 0.0f;

    for (int k0 = 0; k0 < DM; k0 += 16) {
#pragma unroll
        for (int it = 0; it < 8; it++) {
            int idx = tid + it * 256;
            int row = idx >> 4;
            int kk  = idx & 15;
            As[kk * 132 + row] = __bfloat162float(Ah[(size_t)row * DM + k0 + kk]) +
                                 __bfloat162float(Al[(size_t)row * DM + k0 + kk]);
            Bs[kk * 128 + row] = __bfloat162float(Bh[(size_t)row * DM + k0 + kk]) +
                                 __bfloat162float(Bl[(size_t)row * DM + k0 + kk]);
        }
        __syncthreads();
#pragma unroll
        for (int k = 0; k < 16; k++) {
            float a[8], b[8];
            *(float4*)&a[0] = *(float4*)&As[k * 132 + ty * 8];
            *(float4*)&a[4] = *(float4*)&As[k * 132 + ty * 8 + 4];
            *(float4*)&b[0] = *(float4*)&Bs[k * 128 + tx * 8];
            *(float4*)&b[4] = *(float4*)&Bs[k * 128 + tx * 8 + 4];
#pragma unroll
            for (int i = 0; i < 8; i++)
#pragma unroll
                for (int j = 0; j < 8; j++)
                    acc[i][j] += a[i] * b[j];
        }
        __syncthreads();
    }

    float bv[8];
#pragma unroll
    for (int j = 0; j < 8; j++) bv[j] = bias[n0 + tx * 8 + j];

#pragma unroll
    for (int i = 0; i < 8; i++) {
        int m = m0 + ty * 8 + i;
        float* __restrict__ obase;
        size_t base;
        if (split) {
            int h = n0 >> 7;
            int bb = m >> 11;
            int s  = m & (SS - 1);
            obase = (z == 0) ? g_Q : (z == 1) ? g_K : g_V;
            base = ((size_t)(bb * NH + h) * SS + s) * DH + tx * 8;
        } else {
            obase = outp;
            base = (size_t)m * DM + n0 + tx * 8;
        }
        float4 r0, r1;
        r0.x = acc[i][0] + bv[0]; r0.y = acc[i][1] + bv[1];
        r0.z = acc[i][2] + bv[2]; r0.w = acc[i][3] + bv[3];
        r1.x = acc[i][4] + bv[4]; r1.y = acc[i][5] + bv[5];
        r1.z = acc[i][6] + bv[6]; r1.w = acc[i][7] + bv[7];
        *(float4*)(obase + base)     = r0;
        *(float4*)(obase + base + 4) = r1;
    }
#endif
}

// ---------------------------------------------------------------------------
// Attention. a-path: pipelined tcgen05 flash without max-subtraction.
// Grid (SS/128, NH, BB), 256 threads.
// ---------------------------------------------------------------------------
#define AT_LSM 128
#define AT_QH  2048
#define AT_QL  (AT_QH + 32768)
#define AT_KH  (AT_QL + 32768)
#define AT_KL  (AT_KH + 16384)
#define AT_VH  (AT_KL + 16384)
#define AT_VL  (AT_VH + 16384)
#define AT_PH  (AT_VL + 16384)
#define AT_PL  (AT_PH + 16384)
#define ATT_SMEM (AT_PL + 16384)          // 162 KB

#define TM_S 0        // two 64-col S buffers: 0 and 64
#define TM_O 128      // O accumulator: 128 cols

// SIMT fallback layout sizes
#define QS_LD 132
#define PT_LD 68

__global__ __launch_bounds__(256, 1) void attn_kernel(
    const float* __restrict__ mask, float scale)
{
    extern __shared__ char smc[];
    const int tid = threadIdx.x;
    const int h  = blockIdx.y;
    const int b  = blockIdx.z;

#if defined(__CUDA_ARCH_FEAT_SM103_ALL)
    const uint32_t sb = smem_u32(smc);
    const int wid  = tid >> 5;
    const int lane = tid & 31;
    const int sub  = wid & 3;            // TMEM subpartition
    const int half = wid >> 2;           // column half (0/1)
    const int q0   = blockIdx.x << 7;    // 128 q-rows
    const int qrow = sub * 32 + lane;

    const size_t hoff = (size_t)(b * NH + h) * SS * DH;
    const __nv_bfloat16* __restrict__ Qh = g_Qh + hoff;
    const __nv_bfloat16* __restrict__ Ql = g_Ql + hoff;
    const __nv_bfloat16* __restrict__ Kh = g_Kh + hoff;
    const __nv_bfloat16* __restrict__ Kl = g_Kl + hoff;
    const __nv_bfloat16* __restrict__ Vh = g_Vth + hoff;   // [d][S]
    const __nv_bfloat16* __restrict__ Vl = g_Vtl + hoff;
    float* l_sm = (float*)(smc + AT_LSM);

    if (wid == 0) {
        TC_ALLOC(sb, 256);
        TC_RELINQ();
    }
    if (tid == 0) { MBAR_INIT(sb + 8, 1); MBAR_INIT(sb + 16, 1); }

    // K-tile address helpers (per-thread 4 chunks)
    uint32_t ksw[4]; size_t kgo[4];
#pragma unroll
    for (int it = 0; it < 4; it++) {
        int idx = tid + it * 256;        // 0..1023
        int row = idx >> 4;              // 0..63
        int ch  = idx & 15;
        int acol = ch >> 3;
        uint32_t off = ((row >> 3) + acol * 8) * 1024 + (row & 7) * 128 + (ch & 7) * 16;
        ksw[it] = off ^ ((off >> 3) & 0x70);
        kgo[it] = (size_t)row * DH + ch * 8;     // + kv0*DH
    }
    // V-tile address helpers
    uint32_t vsw[4]; size_t vgo[4];
#pragma unroll
    for (int it = 0; it < 4; it++) {
        int idx = tid + it * 256;
        int row = idx >> 3;              // 0..127 (d)
        int ch  = idx & 7;
        uint32_t off = row * 128 + ch * 16;
        vsw[it] = off ^ ((off >> 3) & 0x70);
        vgo[it] = (size_t)row * SS + ch * 8;     // + kv0
    }

    __syncthreads();
    uint32_t tmem;
    asm volatile("ld.shared.b32 %0, [%1];" : "=r"(tmem) : "r"(sb));

    const int coff = half * 32;
    // maskT base for this thread's (column-lane) reads; lane-consecutive in q
    const float* __restrict__ mTb = g_maskT + q0 + qrow;

    // Prefetch maskT tile 0 (32 coalesced LDGs; latency hides behind Q load)
    float mreg[32];
#pragma unroll
    for (int c = 0; c < 32; c++)
        mreg[c] = mTb[(size_t)(coff + c) * SS];

    // Load Q tile [128,128] hi/lo (blocked-atom SW128) + K(0) directly to SMEM
#pragma unroll
    for (int it = 0; it < 8; it++) {
        int idx = tid + it * 256;        // 0..2047
        int row = idx >> 4;              // 0..127
        int ch  = idx & 15;
        int acol = ch >> 3;
        uint32_t off = ((row >> 3) + acol * 16) * 1024 + (row & 7) * 128 + (ch & 7) * 16;
        uint32_t sw = off ^ ((off >> 3) & 0x70);
        size_t g = (size_t)(q0 + row) * DH + ch * 8;
        *(uint4*)(smc + AT_QH + sw) = *(const uint4*)(Qh + g);
        *(uint4*)(smc + AT_QL + sw) = *(const uint4*)(Ql + g);
    }
#pragma unroll
    for (int it = 0; it < 4; it++) {
        *(uint4*)(smc + AT_KH + ksw[it]) = *(const uint4*)(Kh + kgo[it]);
        *(uint4*)(smc + AT_KL + ksw[it]) = *(const uint4*)(Kl + kgo[it]);
    }
    __syncthreads();

    const uint64_t dQh = make_desc(sb + AT_QH);
    const uint64_t dQl = make_desc(sb + AT_QL);
    const uint64_t dKh = make_desc(sb + AT_KH);
    const uint64_t dKl = make_desc(sb + AT_KL);
    const uint64_t dVh = make_desc(sb + AT_VH);
    const uint64_t dVl = make_desc(sb + AT_VL);
    const uint64_t dPh = make_desc(sb + AT_PH);
    const uint64_t dPl = make_desc(sb + AT_PL);

    // Issue S(0)
    if (tid == 0) {
        FENCE_ASYNC();
#pragma unroll
        for (int s = 0; s < 8; s++) {
            uint64_t oa = (s < 4) ? (uint64_t)(s * 2) : (uint64_t)(1024 + (s - 4) * 2);
            uint64_t ob = (s < 4) ? (uint64_t)(s * 2) : (uint64_t)(512 + (s - 4) * 2);
            mma_f16_ss(tmem + TM_S, dQh + oa, dKh + ob, IDESC_N64, s != 0);
            mma_f16_ss(tmem + TM_S, dQh + oa, dKl + ob, IDESC_N64, 1u);
            mma_f16_ss(tmem + TM_S, dQl + oa, dKh + ob, IDESC_N64, 1u);
        }
        TC_COMMIT(sb + 8);
    }

    // Prefetch K(1) and V(0) into registers
    uint4 kbh[4], kbl[4], vbh[4], vbl[4];
#pragma unroll
    for (int it = 0; it < 4; it++) {
        kbh[it] = *(const uint4*)(Kh + (size_t)64 * DH + kgo[it]);
        kbl[it] = *(const uint4*)(Kl + (size_t)64 * DH + kgo[it]);
        vbh[it] = *(const uint4*)(Vh + vgo[it]);
        vbl[it] = *(const uint4*)(Vl + vgo[it]);
    }

    float lacc = 0.0f;
    const float scl2 = scale * 1.4426950408889634f;   // fold scale into log2e

    for (int t = 0; t < 32; t++) {
        // 1. wait S(t)
        MBAR_WAIT(sb + 8, t & 1);
        TC_FENCE_AFTER();

        // 2. store K(t+1), issue S(t+1) into the other S buffer
        if (t < 31) {
#pragma unroll
            for (int it = 0; it < 4; it++) {
                *(uint4*)(smc + AT_KH + ksw[it]) = kbh[it];
                *(uint4*)(smc + AT_KL + ksw[it]) = kbl[it];
            }
        }
        __syncthreads();
        if (t < 31 && tid == 0) {
            FENCE_ASYNC();
            uint32_t sbuf = tmem + TM_S + ((t + 1) & 1) * 64;
#pragma unroll
            for (int s = 0; s < 8; s++) {
                uint64_t oa = (s < 4) ? (uint64_t)(s * 2) : (uint64_t)(1024 + (s - 4) * 2);
                uint64_t ob = (s < 4) ? (uint64_t)(s * 2) : (uint64_t)(512 + (s - 4) * 2);
                mma_f16_ss(sbuf, dQh + oa, dKh + ob, IDESC_N64, s != 0);
                mma_f16_ss(sbuf, dQh + oa, dKl + ob, IDESC_N64, 1u);
                mma_f16_ss(sbuf, dQl + oa, dKh + ob, IDESC_N64, 1u);
            }
            TC_COMMIT(sb + 8);
        }

        // 3. prefetch K(t+2)
        if (t < 30) {
            size_t kadd = (size_t)((t + 2) << 6) * DH;
#pragma unroll
            for (int it = 0; it < 4; it++) {
                kbh[it] = *(const uint4*)(Kh + kadd + kgo[it]);
                kbl[it] = *(const uint4*)(Kl + kadd + kgo[it]);
            }
        }

        // 4. softmax(t): LDTM S, fast exp (fma pipe) with prefetched maskT regs
        float pv0[32];
        {
            uint32_t dr[32];
            TC_LD_X32(dr, tmem + TM_S + (t & 1) * 64 + coff);
            TC_WAIT_LD();
#pragma unroll
            for (int c = 0; c < 32; c += 2) {
                float t0 = fmaf(__uint_as_float(dr[c]),     scl2, mreg[c]);
                float t1 = fmaf(__uint_as_float(dr[c + 1]), scl2, mreg[c + 1]);
                float z0 = t0 + 12582912.0f, z1 = t1 + 12582912.0f;
                float f0 = t0 - (z0 - 12582912.0f);
                float f1 = t1 - (z1 - 12582912.0f);
                float p0 = 1.3333558146e-3f, p1 = 1.3333558146e-3f;
                p0 = fmaf(p0, f0, 9.6181291076e-3f); p1 = fmaf(p1, f1, 9.6181291076e-3f);
                p0 = fmaf(p0, f0, 5.5504108664e-2f); p1 = fmaf(p1, f1, 5.5504108664e-2f);
                p0 = fmaf(p0, f0, 2.4022650696e-1f); p1 = fmaf(p1, f1, 2.4022650696e-1f);
                p0 = fmaf(p0, f0, 6.9314718056e-1f); p1 = fmaf(p1, f1, 6.9314718056e-1f);
                p0 = fmaf(p0, f0, 1.0f);             p1 = fmaf(p1, f1, 1.0f);
                p0 = __int_as_float(__float_as_int(p0) + (__float_as_int(z0) << 23));
                p1 = __int_as_float(__float_as_int(p1) + (__float_as_int(z1) << 23));
                pv0[c] = p0; pv0[c + 1] = p1;
                lacc += p0 + p1;
            }
        }

        // 5. wait PV(t-1) before overwriting V/P SMEM
        if (t > 0) MBAR_WAIT(sb + 16, (t - 1) & 1);

        // 6. store V(t) (from regs) + P(t) (truncation split + PRMT pack)
#pragma unroll
        for (int it = 0; it < 4; it++) {
            *(uint4*)(smc + AT_VH + vsw[it]) = vbh[it];
            *(uint4*)(smc + AT_VL + vsw[it]) = vbl[it];
        }
#pragma unroll
        for (int c = 0; c < 32; c += 2) {
            float p0 = pv0[c], p1 = pv0[c + 1];
            uint32_t b0 = __float_as_int(p0), b1 = __float_as_int(p1);
            uint32_t hp = __byte_perm(b0, b1, 0x7632);            // bf16 pair (truncated)
            float h0 = __int_as_float(b0 & 0xFFFF0000u);
            float h1 = __int_as_float(b1 & 0xFFFF0000u);
            __nv_bfloat162 lo2 = __floats2bfloat162_rn(p0 - h0, p1 - h1);
            uint32_t off = qrow * 128 + (coff + c) * 2;
            uint32_t sw = off ^ ((off >> 3) & 0x70);
            *(uint32_t*)(smc + AT_PH + sw) = hp;
            *(uint32_t*)(smc + AT_PL + sw) = *(uint32_t*)&lo2;
        }
        __syncthreads();

        // 7. issue PV(t)
        if (tid == 0) {
            FENCE_ASYNC();
#pragma unroll
            for (int s = 0; s < 4; s++) {
                uint64_t o2 = (uint64_t)(s * 2);
                mma_f16_ss(tmem + TM_O, dPh + o2, dVh + o2, IDESC_N128, !(t == 0 && s == 0));
                mma_f16_ss(tmem + TM_O, dPh + o2, dVl + o2, IDESC_N128, 1u);
                mma_f16_ss(tmem + TM_O, dPl + o2, dVh + o2, IDESC_N128, 1u);
            }
            TC_COMMIT(sb + 16);
        }

        // 8. prefetch V(t+1) and maskT(t+1)
        if (t < 31) {
            size_t vadd = (size_t)((t + 1) << 6);
#pragma unroll
            for (int it = 0; it < 4; it++) {
                vbh[it] = *(const uint4*)(Vh + vadd + vgo[it]);
                vbl[it] = *(const uint4*)(Vl + vadd + vgo[it]);
            }
            const float* mTt = mTb + (size_t)((t + 1) << 6) * SS;
#pragma unroll
            for (int c = 0; c < 32; c++)
                mreg[c] = mTt[(size_t)(coff + c) * SS];
        }
    }

    MBAR_WAIT(sb + 16, 31 & 1);
    TC_FENCE_AFTER();

    // combine l halves
    l_sm[half * 128 + qrow] = lacc;
    __syncthreads();
    float inv = 1.0f / (l_sm[qrow] + l_sm[128 + qrow]);

    // write ctx (rows qrow, d cols half*64..+63) as bf16 hi/lo
    {
        uint32_t d0[32], d1[32];
        TC_LD_X32(d0, tmem + TM_O + half * 64);
        TC_LD_X32(d1, tmem + TM_O + half * 64 + 32);
        TC_WAIT_LD();
        size_t base = ((size_t)b * SS + q0 + qrow) * DM + h * DH + half * 64;
#pragma unroll
        for (int j = 0; j < 64; j += 2) {
            float v0 = __uint_as_float(j < 32 ? d0[j]     : d1[j - 32]) * inv;
            float v1 = __uint_as_float(j < 31 ? d0[j + 1] : d1[j + 1 - 32]) * inv;
            __nv_bfloat16 h0 = __float2bfloat16(v0);
            __nv_bfloat16 h1 = __float2bfloat16(v1);
            __nv_bfloat16 l0 = __float2bfloat16(v0 - __bfloat162float(h0));
            __nv_bfloat16 l1 = __float2bfloat16(v1 - __bfloat162float(h1));
            __nv_bfloat16 hp[2] = {h0, h1}, lp[2] = {l0, l1};
            *(uint32_t*)(g_Ch + base + j) = *(uint32_t*)hp;
            *(uint32_t*)(g_Cl + base + j) = *(uint32_t*)lp;
        }
    }
    __syncthreads();
    if (wid == 0) TC_DEALLOC(tmem, 256);

#else
    // ---------------- SIMT fp32 fallback (two 64-row halves) ----------------
    float* sm = (float*)smc;
    float* Qs = sm;
    float* Ks = Qs + 64 * QS_LD;
    float* Vs = Ks + 64 * QS_LD;
    float* Pt = Vs + 64 * 128;

    const int ty = tid >> 4;
    const int tx = tid & 15;
    const size_t headoff = (size_t)(b * NH + h) * SS * DH;
    const float* __restrict__ Qg = g_Q + headoff;
    const float* __restrict__ Kg = g_K + headoff;
    const float* __restrict__ Vg = g_V + headoff;

    for (int qh = 0; qh < 2; qh++) {
        const int q0 = (blockIdx.x << 7) + (qh << 6);
        __syncthreads();
#pragma unroll
        for (int it = 0; it < 8; it++) {
            int idx = tid + it * 256;
            int row = idx >> 5;
            int d4  = (idx & 31) << 2;
            *(float4*)&Qs[row * QS_LD + d4] =
                *(const float4*)(Qg + (size_t)(q0 + row) * DH + d4);
        }

        const int r0 = ty * 4;
        float m_i[4], l_i[4], acc[4][8];
#pragma unroll
        for (int i = 0; i < 4; i++) {
            m_i[i] = -1e30f;
            l_i[i] = 0.0f;
#pragma unroll
            for (int j = 0; j < 8; j++) acc[i][j] = 0.0f;
        }

        for (int kv0 = 0; kv0 < SS; kv0 += 64) {
            __syncthreads();
#pragma unroll
            for (int it = 0; it < 8; it++) {
                int idx = tid + it * 256;
                int row = idx >> 5;
                int d4  = (idx & 31) << 2;
                *(float4*)&Ks[row * QS_LD + d4] =
                    *(const float4*)(Kg + (size_t)(kv0 + row) * DH + d4);
                *(float4*)&Vs[row * 128 + d4] =
                    *(const float4*)(Vg + (size_t)(kv0 + row) * DH + d4);
            }
            __syncthreads();

            float s[4][4];
#pragma unroll
            for (int i = 0; i < 4; i++)
#pragma unroll
                for (int j = 0; j < 4; j++) s[i][j] = 0.0f;

#pragma unroll 8
            for (int d = 0; d < DH; d += 4) {
                float4 q[4], k[4];
#pragma unroll
                for (int i = 0; i < 4; i++) q[i] = *(float4*)&Qs[(r0 + i) * QS_LD + d];
#pragma unroll
                for (int j = 0; j < 4; j++) k[j] = *(float4*)&Ks[(tx + 16 * j) * QS_LD + d];
#pragma unroll
                for (int i = 0; i < 4; i++)
#pragma unroll
                    for (int j = 0; j < 4; j++)
                        s[i][j] += q[i].x * k[j].x + q[i].y * k[j].y +
                                   q[i].z * k[j].z + q[i].w * k[j].w;
            }

#pragma unroll
            for (int i = 0; i < 4; i++) {
                const float* mrow = mask + (size_t)(q0 + r0 + i) * SS + kv0;
#pragma unroll
                for (int j = 0; j < 4; j++)
                    s[i][j] = s[i][j] * scale + mrow[tx + 16 * j];

                float mx = fmaxf(fmaxf(s[i][0], s[i][1]), fmaxf(s[i][2], s[i][3]));
#pragma unroll
                for (int o = 1; o < 16; o <<= 1)
                    mx = fmaxf(mx, __shfl_xor_sync(0xffffffffu, mx, o));
                float mnew = fmaxf(m_i[i], mx);

                float sum = 0.0f;
#pragma unroll
                for (int j = 0; j < 4; j++) {
                    s[i][j] = __expf(s[i][j] - mnew);
                    sum += s[i][j];
                }
#pragma unroll
                for (int o = 1; o < 16; o <<= 1)
                    sum += __shfl_xor_sync(0xffffffffu, sum, o);

                float alpha = __expf(m_i[i] - mnew);
                l_i[i] = l_i[i] * alpha + sum;
                m_i[i] = mnew;
#pragma unroll
                for (int j = 0; j < 8; j++) acc[i][j] *= alpha;
            }

#pragma unroll
            for (int j = 0; j < 4; j++)
#pragma unroll
                for (int i = 0; i < 4; i++)
                    Pt[(tx + 16 * j) * PT_LD + r0 + i] = s[i][j];
            __syncthreads();

#pragma unroll 8
            for (int c = 0; c < 64; c++) {
                float4 p  = *(float4*)&Pt[c * PT_LD + r0];
                float4 v0 = *(float4*)&Vs[c * 128 + tx * 8];
                float4 v1 = *(float4*)&Vs[c * 128 + tx * 8 + 4];
                float pa[4] = {p.x, p.y, p.z, p.w};
                float va[8] = {v0.x, v0.y, v0.z, v0.w, v1.x, v1.y, v1.z, v1.w};
#pragma unroll
                for (int i = 0; i < 4; i++)
#pragma unroll
                    for (int j = 0; j < 8; j++)
                        acc[i][j] += pa[i] * va[j];
            }
        }

#pragma unroll
        for (int i = 0; i < 4; i++) {
            float inv = 1.0f / l_i[i];
            size_t base = ((size_t)b * SS + q0 + r0 + i) * DM + h * DH + tx * 8;
            __nv_bfloat16 hh[8], ll[8];
#pragma unroll
            for (int j = 0; j < 8; j++) {
                float v = acc[i][j] * inv;
                hh[j] = __float2bfloat16(v);
                ll[j] = __float2bfloat16(v - __bfloat162float(hh[j]));
            }
            *(uint4*)&g_Ch[base] = *(uint4*)hh;
            *(uint4*)&g_Cl[base] = *(uint4*)ll;
        }
    }
#endif
}

// ---------------------------------------------------------------------------
extern "C" void kernel_launch(void* const* d_in, const int* in_sizes, int n_in,
                              void* d_out, int out_size)
{
    const float* x    = (const float*)d_in[0];
    const float* mask = (const float*)d_in[1];
    const float* wq   = (const float*)d_in[2];
    const float* bq   = (const float*)d_in[3];
    const float* wk   = (const float*)d_in[4];
    const float* bk   = (const float*)d_in[5];
    const float* wv   = (const float*)d_in[6];
    const float* bv   = (const float*)d_in[7];
    const float* wo   = (const float*)d_in[8];
    const float* bo   = (const float*)d_in[9];
    float* out = (float*)d_out;

    cudaFuncSetAttribute(tc_gemm, cudaFuncAttributeMaxDynamicSharedMemorySize, GEMM_SMEM);
    cudaFuncSetAttribute(attn_kernel, cudaFuncAttributeMaxDynamicSharedMemorySize, ATT_SMEM);

    split_x_kernel<<<(MT * DM) / (256 * 4), 256>>>(x);
    wsplit_kernel<<<dim3(64, 64, 4), 256>>>(wq, wk, wv, wo);
    mtrans_kernel<<<dim3(SS / 32, SS / 32), 256>>>(mask);

    // QKV projections
    tc_gemm<<<dim3(16, 32, 3), 256, GEMM_SMEM>>>(bq, bk, bv, nullptr, 0, 1);

    // attention
    const float scale = 0.08838834764831845f;  // 1/sqrt(128)
    attn_kernel<<<dim3(SS / 128, NH, BB), 256, ATT_SMEM>>>(mask, scale);

    // output projection
    tc_gemm<<<dim3(16, 32, 1), 256, GEMM_SMEM>>>(bo, bo, bo, out, 3, 0);
}

// round 13
// speedup vs baseline: 1.2928x; 1.2928x over previous
#include <cuda_runtime.h>
#include <cuda_bf16.h>
#include <cstdint>

#define DM 2048
#define NH 16
#define DH 128
#define BB 2
#define SS 2048
#define MT (BB*SS)   // 4096 rows

// ---------------------------------------------------------------------------
// Device scratch (allocation-free per harness rules)
// ---------------------------------------------------------------------------
__device__ float g_Q[(size_t)MT*DM];                 // fp32 (fallback path only)
__device__ float g_K[(size_t)MT*DM];
__device__ float g_V[(size_t)MT*DM];
__device__ float g_maskT[(size_t)SS*SS];             // mask^T * log2e
__device__ __nv_bfloat16 g_Qh[(size_t)MT*DM];        // [B,H,S,d] splits (a-path)
__device__ __nv_bfloat16 g_Ql[(size_t)MT*DM];
__device__ __nv_bfloat16 g_Kh[(size_t)MT*DM];
__device__ __nv_bfloat16 g_Kl[(size_t)MT*DM];
__device__ __nv_bfloat16 g_Vth[(size_t)MT*DM];       // V^T [B,H,d,S]
__device__ __nv_bfloat16 g_Vtl[(size_t)MT*DM];
__device__ __nv_bfloat16 g_Xh[(size_t)MT*DM];        // x split  [M,K]
__device__ __nv_bfloat16 g_Xl[(size_t)MT*DM];
__device__ __nv_bfloat16 g_Ch[(size_t)MT*DM];        // attention ctx split [M,K]
__device__ __nv_bfloat16 g_Cl[(size_t)MT*DM];
__device__ __nv_bfloat16 g_Wh[(size_t)4*DM*DM];      // transposed weights [N,K], z: q,k,v,o
__device__ __nv_bfloat16 g_Wl[(size_t)4*DM*DM];

// ---------------------------------------------------------------------------
// tcgen05 helpers — only in the sm_103a feature pass; plain sm_103 pass gets
// SIMT fallback bodies so both ptxas passes compile.
// ---------------------------------------------------------------------------
__device__ __forceinline__ uint32_t smem_u32(const void* p) {
    uint32_t a;
    asm("{ .reg .u64 t; cvta.to.shared.u64 t, %1; cvt.u32.u64 %0, t; }" : "=r"(a) : "l"(p));
    return a;
}

#if defined(__CUDA_ARCH_FEAT_SM103_ALL)

#define TC_ALLOC(sm, n)  asm volatile("tcgen05.alloc.cta_group::1.sync.aligned.shared::cta.b32 [%0], %1;" :: "r"(sm), "r"(n) : "memory")
#define TC_RELINQ()      asm volatile("tcgen05.relinquish_alloc_permit.cta_group::1.sync.aligned;")
#define TC_DEALLOC(t, n) asm volatile("tcgen05.dealloc.cta_group::1.sync.aligned.b32 %0, %1;" :: "r"(t), "r"(n))
#define TC_COMMIT(mb)    asm volatile("tcgen05.commit.cta_group::1.mbarrier::arrive::one.shared::cluster.b64 [%0];" :: "r"(mb) : "memory")
#define TC_FENCE_AFTER() asm volatile("tcgen05.fence::after_thread_sync;" ::: "memory")
#define TC_WAIT_LD()     asm volatile("tcgen05.wait::ld.sync.aligned;" ::: "memory")
#define MBAR_INIT(mb, c) asm volatile("mbarrier.init.shared.b64 [%0], %1;" :: "r"(mb), "r"(c) : "memory")
#define FENCE_ASYNC()    asm volatile("fence.proxy.async.shared::cta;" ::: "memory")

#define MBAR_WAIT(mb, ph) do {                                                   \
    uint32_t _m = (mb), _p = (ph), _d;                                           \
    asm volatile("{\n\t.reg .pred p;\n\t"                                        \
        "mbarrier.try_wait.parity.acquire.cta.shared::cta.b64 p, [%1], %2;\n\t"  \
        "selp.b32 %0, 1, 0, p;\n\t}"                                             \
        : "=r"(_d) : "r"(_m), "r"(_p) : "memory");                               \
    if (!_d) {                                                                   \
        asm volatile("{\n\t.reg .pred P1;\n\t"                                   \
        "WL_%=:\n\t"                                                             \
        "mbarrier.try_wait.parity.acquire.cta.shared::cta.b64 P1, [%0], %1, 0x989680;\n\t" \
        "@P1 bra.uni WD_%=;\n\t"                                                 \
        "bra.uni WL_%=;\n\t"                                                     \
        "WD_%=:\n\t}" :: "r"(_m), "r"(_p) : "memory");                           \
    }                                                                            \
} while (0)

#define TC_LD_X32(r, ta)                                                         \
    asm volatile("tcgen05.ld.sync.aligned.32x32b.x32.b32 "                       \
        "{%0, %1, %2, %3, %4, %5, %6, %7, "                                      \
        " %8, %9, %10, %11, %12, %13, %14, %15, "                                \
        " %16, %17, %18, %19, %20, %21, %22, %23, "                              \
        " %24, %25, %26, %27, %28, %29, %30, %31}, [%32];"                       \
        : "=r"((r)[0]), "=r"((r)[1]), "=r"((r)[2]), "=r"((r)[3]),                \
          "=r"((r)[4]), "=r"((r)[5]), "=r"((r)[6]), "=r"((r)[7]),                \
          "=r"((r)[8]), "=r"((r)[9]), "=r"((r)[10]), "=r"((r)[11]),              \
          "=r"((r)[12]), "=r"((r)[13]), "=r"((r)[14]), "=r"((r)[15]),            \
          "=r"((r)[16]), "=r"((r)[17]), "=r"((r)[18]), "=r"((r)[19]),            \
          "=r"((r)[20]), "=r"((r)[21]), "=r"((r)[22]), "=r"((r)[23]),            \
          "=r"((r)[24]), "=r"((r)[25]), "=r"((r)[26]), "=r"((r)[27]),            \
          "=r"((r)[28]), "=r"((r)[29]), "=r"((r)[30]), "=r"((r)[31])             \
        : "r"(ta))

// SW128 K-major SMEM descriptor (layout=2, version=1, SBO=64, LBO=1)
static __device__ __forceinline__ uint64_t make_desc(uint32_t addr) {
    const uint64_t base =
        (uint64_t(2) << 61) | (uint64_t(1) << 46) | (uint64_t(64) << 32) | (uint64_t(1) << 16);
    return base | ((uint64_t)(addr >> 4) & 0x3FFF);
}

// idesc: dtype=F32, atype=btype=BF16, M=128, N variable
#define IDESC_N128 ((1u<<4) | (1u<<7) | (1u<<10) | ((128u/8)<<17) | ((128u/16)<<24))
#define IDESC_N64  ((1u<<4) | (1u<<7) | (1u<<10) | ((64u/8)<<17)  | ((128u/16)<<24))

__device__ __forceinline__ void mma_f16_ss(uint32_t d, uint64_t a, uint64_t b,
                                           uint32_t idesc, uint32_t en) {
    asm volatile(
        "{\n\t.reg .pred p;\n\t"
        "setp.ne.u32 p, %4, 0;\n\t"
        "tcgen05.mma.cta_group::1.kind::f16 [%0], %1, %2, %3, {%5,%5,%5,%5}, p;\n\t}"
        :: "r"(d), "l"(a), "l"(b), "r"(idesc), "r"(en), "r"(0u) : "memory");
}

#endif  // __CUDA_ARCH_FEAT_SM103_ALL

// ---------------------------------------------------------------------------
// Prep 1: split x into bf16 hi/lo
// ---------------------------------------------------------------------------
__global__ void split_x_kernel(const float* __restrict__ x)
{
    size_t i = ((size_t)blockIdx.x * 256 + threadIdx.x) * 4;
    float4 v = *(const float4*)(x + i);
    __nv_bfloat16 h[4], l[4];
    float vv[4] = {v.x, v.y, v.z, v.w};
#pragma unroll
    for (int j = 0; j < 4; j++) {
        h[j] = __float2bfloat16(vv[j]);
        l[j] = __float2bfloat16(vv[j] - __bfloat162float(h[j]));
    }
    *(uint2*)&g_Xh[i] = *(uint2*)h;
    *(uint2*)&g_Xl[i] = *(uint2*)l;
}

// ---------------------------------------------------------------------------
// Prep 2: transpose + split weights. W[K,N] fp32 -> Wt[N,K] bf16 hi/lo.
// ---------------------------------------------------------------------------
__global__ void wsplit_kernel(const float* __restrict__ wq, const float* __restrict__ wk,
                              const float* __restrict__ wv, const float* __restrict__ wo)
{
    __shared__ float t[32][33];
    const int z = blockIdx.z;
    const float* __restrict__ W = (z == 0) ? wq : (z == 1) ? wk : (z == 2) ? wv : wo;
    const int n0 = blockIdx.x << 5;
    const int k0 = blockIdx.y << 5;
    const int tx = threadIdx.x & 31;
    const int ty = threadIdx.x >> 5;   // 0..7

#pragma unroll
    for (int r = ty; r < 32; r += 8)
        t[r][tx] = W[(size_t)(k0 + r) * DM + n0 + tx];
    __syncthreads();

    const size_t zoff = (size_t)z * DM * DM;
#pragma unroll
    for (int r = ty; r < 32; r += 8) {
        float v = t[tx][r];    // = W[k0+tx][n0+r]
        __nv_bfloat16 h = __float2bfloat16(v);
        float lo = v - __bfloat162float(h);
        size_t o = zoff + (size_t)(n0 + r) * DM + k0 + tx;
        g_Wh[o] = h;
        g_Wl[o] = __float2bfloat16(lo);
    }
}

// ---------------------------------------------------------------------------
// Prep 3: maskT[kv][q] = mask[q][kv] * log2e.
// ---------------------------------------------------------------------------
__global__ void mtrans_kernel(const float* __restrict__ mask)
{
    __shared__ float t[32][33];
    const int x0 = blockIdx.x << 5;     // kv tile
    const int y0 = blockIdx.y << 5;     // q tile
    const int tx = threadIdx.x & 31;
    const int ty = threadIdx.x >> 5;    // 0..7

#pragma unroll
    for (int r = ty; r < 32; r += 8)
        t[r][tx] = mask[(size_t)(y0 + r) * SS + x0 + tx];
    __syncthreads();
#pragma unroll
    for (int r = ty; r < 32; r += 8)
        g_maskT[(size_t)(x0 + r) * SS + y0 + tx] =
            t[tx][r] * 1.4426950408889634f;
}

// ---------------------------------------------------------------------------
// GEMM: BM=256 per CTA — two 128-row M-tiles sharing one 128-col weight tile.
// R11's proven single-buffer register-prefetch pipeline; 6 MMA dispatches per
// k-substep (2 M-tiles x 3 splits). Halves weight L2 traffic vs BM=128.
// Grid (N/128, M/256, z). TMEM: D0 @ cols 0-127, D1 @ cols 128-255.
// ---------------------------------------------------------------------------
#define GK 64
#define SM_MBAR 8
#define SM_A    1024
#define SM_TILE 16384                     // 128*64*2B
#define GEMM_SMEM (1024 + 6*SM_TILE)      // 97.25 KB -> 1 CTA/SM

__global__ __launch_bounds__(256, 1) void tc_gemm(
    const float* __restrict__ b0, const float* __restrict__ b1, const float* __restrict__ b2,
    float* __restrict__ outp, int wsel, int split)
{
    extern __shared__ char smem[];
    const int tid = threadIdx.x;
    const int z   = blockIdx.z;
    const int m0  = blockIdx.y << 8;       // 256 rows per CTA
    const int n0  = blockIdx.x << 7;

    const __nv_bfloat16* __restrict__ Abase_h = (split ? g_Xh : g_Ch);
    const __nv_bfloat16* __restrict__ Abase_l = (split ? g_Xl : g_Cl);
    const size_t wz = (size_t)(wsel + z) * DM * DM;
    const float* __restrict__ bias = (z == 0) ? b0 : (z == 1) ? b1 : b2;

    // 6 source tiles: A0h, A0l, A1h, A1l, Bh, Bl
    const __nv_bfloat16* __restrict__ tp[6] = {
        Abase_h + (size_t)m0 * DM,
        Abase_l + (size_t)m0 * DM,
        Abase_h + (size_t)(m0 + 128) * DM,
        Abase_l + (size_t)(m0 + 128) * DM,
        g_Wh + wz + (size_t)n0 * DM,
        g_Wl + wz + (size_t)n0 * DM
    };

#if defined(__CUDA_ARCH_FEAT_SM103_ALL)
    // ------------------------- tcgen05 path -------------------------
    const uint32_t sb = smem_u32(smem);
    const int wid = tid >> 5;

    if (wid == 0) {
        TC_ALLOC(sb, 256);
        TC_RELINQ();
    }
    if (tid == 0) MBAR_INIT(sb + SM_MBAR, 1);

    // per-thread tile addresses (4 chunks per tile)
    uint32_t tsw[4]; size_t tgo[4];
#pragma unroll
    for (int it = 0; it < 4; it++) {
        int idx = tid + it * 256;          // 0..1023
        int row = idx >> 3;                // 0..127
        int cc  = idx & 7;                 // 16B chunk
        uint32_t off = row * 128 + cc * 16;
        tsw[it] = off ^ ((off >> 3) & 0x70);
        tgo[it] = (size_t)row * DM + cc * 8;   // + k0
    }

    __syncthreads();
    uint32_t tmem;
    asm volatile("ld.shared.b32 %0, [%1];" : "=r"(tmem) : "r"(sb));

    uint64_t dt[6];
#pragma unroll
    for (int q = 0; q < 6; q++)
        dt[q] = make_desc(sb + SM_A + q * SM_TILE);

    const int NIT = DM / GK;               // 32
    for (int t = 0; t < NIT; t++) {
        const size_t k0 = (size_t)t * GK;

        // prefetch all 6 tiles into registers (overlaps in-flight MMA)
        uint4 rr[6][4];
#pragma unroll
        for (int q = 0; q < 6; q++)
#pragma unroll
            for (int it = 0; it < 4; it++)
                rr[q][it] = *(const uint4*)(tp[q] + tgo[it] + k0);

        // wait for MMA(t-1) to finish reading SMEM
        if (t > 0) MBAR_WAIT(sb + SM_MBAR, (t - 1) & 1);

#pragma unroll
        for (int q = 0; q < 6; q++)
#pragma unroll
            for (int it = 0; it < 4; it++)
                *(uint4*)(smem + SM_A + q * SM_TILE + tsw[it]) = rr[q][it];
        __syncthreads();

        if (tid == 0) {
            FENCE_ASYNC();
#pragma unroll
            for (int s = 0; s < 4; s++) {
                uint64_t oa = (uint64_t)(s * 2);
                uint32_t en0 = !(t == 0 && s == 0);
                // D0 = A0 @ B
                mma_f16_ss(tmem,       dt[0] + oa, dt[4] + oa, IDESC_N128, en0);
                mma_f16_ss(tmem,       dt[0] + oa, dt[5] + oa, IDESC_N128, 1u);
                mma_f16_ss(tmem,       dt[1] + oa, dt[4] + oa, IDESC_N128, 1u);
                // D1 = A1 @ B
                mma_f16_ss(tmem + 128, dt[2] + oa, dt[4] + oa, IDESC_N128, en0);
                mma_f16_ss(tmem + 128, dt[2] + oa, dt[5] + oa, IDESC_N128, 1u);
                mma_f16_ss(tmem + 128, dt[3] + oa, dt[4] + oa, IDESC_N128, 1u);
            }
            TC_COMMIT(sb + SM_MBAR);
        }
    }
    MBAR_WAIT(sb + SM_MBAR, (NIT - 1) & 1);
    TC_FENCE_AFTER();

    // Epilogue: warps 0-3 -> tile 0, warps 4-7 -> tile 1.
    {
        const int tile = wid >> 2;
        const int w4   = wid & 3;
        const int lid  = tid & 31;
        const int m = m0 + tile * 128 + w4 * 32 + lid;
        const int bb = m >> 11;
        const int s  = m & (SS - 1);
        const int h  = n0 >> 7;
#pragma unroll
        for (int cc = 0; cc < 4; cc++) {
            uint32_t dr[32];
            TC_LD_X32(dr, tmem + tile * 128 + cc * 32);
            TC_WAIT_LD();
            int coff = cc * 32;
            if (!split) {
                size_t base = (size_t)m * DM + n0 + coff;
#pragma unroll
                for (int j = 0; j < 32; j += 4) {
                    float4 r;
                    r.x = __uint_as_float(dr[j + 0]) + bias[n0 + coff + j + 0];
                    r.y = __uint_as_float(dr[j + 1]) + bias[n0 + coff + j + 1];
                    r.z = __uint_as_float(dr[j + 2]) + bias[n0 + coff + j + 2];
                    r.w = __uint_as_float(dr[j + 3]) + bias[n0 + coff + j + 3];
                    *(float4*)(outp + base + j) = r;
                }
            } else if (z == 2) {
                // V^T: [B,H][d][S], d = coff+j
                size_t vbase = (size_t)(bb * NH + h) * DH * SS + s;
#pragma unroll
                for (int j = 0; j < 32; j++) {
                    float v = __uint_as_float(dr[j]) + bias[n0 + coff + j];
                    __nv_bfloat16 hh = __float2bfloat16(v);
                    size_t o = vbase + (size_t)(coff + j) * SS;
                    g_Vth[o] = hh;
                    g_Vtl[o] = __float2bfloat16(v - __bfloat162float(hh));
                }
            } else {
                // Q/K: [B,H,S,d] bf16 splits, pair stores
                __nv_bfloat16* __restrict__ oh = (z == 0) ? g_Qh : g_Kh;
                __nv_bfloat16* __restrict__ ol = (z == 0) ? g_Ql : g_Kl;
                size_t base = ((size_t)(bb * NH + h) * SS + s) * DH + coff;
#pragma unroll
                for (int j = 0; j < 32; j += 2) {
                    float v0 = __uint_as_float(dr[j])     + bias[n0 + coff + j];
                    float v1 = __uint_as_float(dr[j + 1]) + bias[n0 + coff + j + 1];
                    __nv_bfloat16 h0 = __float2bfloat16(v0);
                    __nv_bfloat16 h1 = __float2bfloat16(v1);
                    __nv_bfloat16 l0 = __float2bfloat16(v0 - __bfloat162float(h0));
                    __nv_bfloat16 l1 = __float2bfloat16(v1 - __bfloat162float(h1));
                    __nv_bfloat16 hp[2] = {h0, h1}, lp[2] = {l0, l1};
                    *(uint32_t*)(oh + base + j) = *(uint32_t*)hp;
                    *(uint32_t*)(ol + base + j) = *(uint32_t*)lp;
                }
            }
        }
    }
    __syncthreads();
    if (wid == 0) TC_DEALLOC(tmem, 256);

#else
    // ------------------------- SIMT fallback (sm_103 pass) -------------------------
    float* As = (float*)smem;            // [16][132]
    float* Bs = As + 16 * 132;           // [16][128]
    const int ty = tid >> 4;
    const int tx = tid & 15;

    for (int halfm = 0; halfm < 2; halfm++) {
        const __nv_bfloat16* __restrict__ Ah = tp[halfm * 2];
        const __nv_bfloat16* __restrict__ Al = tp[halfm * 2 + 1];
        const __nv_bfloat16* __restrict__ Bh = tp[4];
        const __nv_bfloat16* __restrict__ Bl = tp[5];
        const int m0h = m0 + halfm * 128;

        float acc[8][8];
#pragma unroll
        for (int i = 0; i < 8; i++)
#pragma unroll
            for (int j = 0; j < 8; j++) acc[i][j] = 0.0f;

        __syncthreads();
        for (int k0 = 0; k0 < DM; k0 += 16) {
#pragma unroll
            for (int it = 0; it < 8; it++) {
                int idx = tid + it * 256;
                int row = idx >> 4;
                int kk  = idx & 15;
                As[kk * 132 + row] = __bfloat162float(Ah[(size_t)row * DM + k0 + kk]) +
                                     __bfloat162float(Al[(size_t)row * DM + k0 + kk]);
                Bs[kk * 128 + row] = __bfloat162float(Bh[(size_t)row * DM + k0 + kk]) +
                                     __bfloat162float(Bl[(size_t)row * DM + k0 + kk]);
            }
            __syncthreads();
#pragma unroll
            for (int k = 0; k < 16; k++) {
                float a[8], b[8];
                *(float4*)&a[0] = *(float4*)&As[k * 132 + ty * 8];
                *(float4*)&a[4] = *(float4*)&As[k * 132 + ty * 8 + 4];
                *(float4*)&b[0] = *(float4*)&Bs[k * 128 + tx * 8];
                *(float4*)&b[4] = *(float4*)&Bs[k * 128 + tx * 8 + 4];
#pragma unroll
                for (int i = 0; i < 8; i++)
#pragma unroll
                    for (int j = 0; j < 8; j++)
                        acc[i][j] += a[i] * b[j];
            }
            __syncthreads();
        }

        float bv[8];
#pragma unroll
        for (int j = 0; j < 8; j++) bv[j] = bias[n0 + tx * 8 + j];

#pragma unroll
        for (int i = 0; i < 8; i++) {
            int m = m0h + ty * 8 + i;
            float* __restrict__ obase;
            size_t base;
            if (split) {
                int h = n0 >> 7;
                int bb = m >> 11;
                int s  = m & (SS - 1);
                obase = (z == 0) ? g_Q : (z == 1) ? g_K : g_V;
                base = ((size_t)(bb * NH + h) * SS + s) * DH + tx * 8;
            } else {
                obase = outp;
                base = (size_t)m * DM + n0 + tx * 8;
            }
            float4 r0, r1;
            r0.x = acc[i][0] + bv[0]; r0.y = acc[i][1] + bv[1];
            r0.z = acc[i][2] + bv[2]; r0.w = acc[i][3] + bv[3];
            r1.x = acc[i][4] + bv[4]; r1.y = acc[i][5] + bv[5];
            r1.z = acc[i][6] + bv[6]; r1.w = acc[i][7] + bv[7];
            *(float4*)(obase + base)     = r0;
            *(float4*)(obase + base + 4) = r1;
        }
    }
#endif
}

// ---------------------------------------------------------------------------
// Attention. a-path: pipelined tcgen05 flash without max-subtraction.
// Grid (SS/128, NH, BB), 256 threads.  (Unchanged from the R11 passing version.)
// ---------------------------------------------------------------------------
#define AT_LSM 128
#define AT_QH  2048
#define AT_QL  (AT_QH + 32768)
#define AT_KH  (AT_QL + 32768)
#define AT_KL  (AT_KH + 16384)
#define AT_VH  (AT_KL + 16384)
#define AT_VL  (AT_VH + 16384)
#define AT_PH  (AT_VL + 16384)
#define AT_PL  (AT_PH + 16384)
#define ATT_SMEM (AT_PL + 16384)          // 162 KB

#define TM_S 0        // two 64-col S buffers: 0 and 64
#define TM_O 128      // O accumulator: 128 cols

// SIMT fallback layout sizes
#define QS_LD 132
#define PT_LD 68

__global__ __launch_bounds__(256, 1) void attn_kernel(
    const float* __restrict__ mask, float scale)
{
    extern __shared__ char smc[];
    const int tid = threadIdx.x;
    const int h  = blockIdx.y;
    const int b  = blockIdx.z;

#if defined(__CUDA_ARCH_FEAT_SM103_ALL)
    const uint32_t sb = smem_u32(smc);
    const int wid  = tid >> 5;
    const int lane = tid & 31;
    const int sub  = wid & 3;            // TMEM subpartition
    const int half = wid >> 2;           // column half (0/1)
    const int q0   = blockIdx.x << 7;    // 128 q-rows
    const int qrow = sub * 32 + lane;

    const size_t hoff = (size_t)(b * NH + h) * SS * DH;
    const __nv_bfloat16* __restrict__ Qh = g_Qh + hoff;
    const __nv_bfloat16* __restrict__ Ql = g_Ql + hoff;
    const __nv_bfloat16* __restrict__ Kh = g_Kh + hoff;
    const __nv_bfloat16* __restrict__ Kl = g_Kl + hoff;
    const __nv_bfloat16* __restrict__ Vh = g_Vth + hoff;   // [d][S]
    const __nv_bfloat16* __restrict__ Vl = g_Vtl + hoff;
    float* l_sm = (float*)(smc + AT_LSM);

    if (wid == 0) {
        TC_ALLOC(sb, 256);
        TC_RELINQ();
    }
    if (tid == 0) { MBAR_INIT(sb + 8, 1); MBAR_INIT(sb + 16, 1); }

    // K-tile address helpers (per-thread 4 chunks)
    uint32_t ksw[4]; size_t kgo[4];
#pragma unroll
    for (int it = 0; it < 4; it++) {
        int idx = tid + it * 256;        // 0..1023
        int row = idx >> 4;              // 0..63
        int ch  = idx & 15;
        int acol = ch >> 3;
        uint32_t off = ((row >> 3) + acol * 8) * 1024 + (row & 7) * 128 + (ch & 7) * 16;
        ksw[it] = off ^ ((off >> 3) & 0x70);
        kgo[it] = (size_t)row * DH + ch * 8;     // + kv0*DH
    }
    // V-tile address helpers
    uint32_t vsw[4]; size_t vgo[4];
#pragma unroll
    for (int it = 0; it < 4; it++) {
        int idx = tid + it * 256;
        int row = idx >> 3;              // 0..127 (d)
        int ch  = idx & 7;
        uint32_t off = row * 128 + ch * 16;
        vsw[it] = off ^ ((off >> 3) & 0x70);
        vgo[it] = (size_t)row * SS + ch * 8;     // + kv0
    }

    __syncthreads();
    uint32_t tmem;
    asm volatile("ld.shared.b32 %0, [%1];" : "=r"(tmem) : "r"(sb));

    const int coff = half * 32;
    // maskT base for this thread's (column-lane) reads; lane-consecutive in q
    const float* __restrict__ mTb = g_maskT + q0 + qrow;

    // Prefetch maskT tile 0 (32 coalesced LDGs; latency hides behind Q load)
    float mreg[32];
#pragma unroll
    for (int c = 0; c < 32; c++)
        mreg[c] = mTb[(size_t)(coff + c) * SS];

    // Load Q tile [128,128] hi/lo (blocked-atom SW128) + K(0) directly to SMEM
#pragma unroll
    for (int it = 0; it < 8; it++) {
        int idx = tid + it * 256;        // 0..2047
        int row = idx >> 4;              // 0..127
        int ch  = idx & 15;
        int acol = ch >> 3;
        uint32_t off = ((row >> 3) + acol * 16) * 1024 + (row & 7) * 128 + (ch & 7) * 16;
        uint32_t sw = off ^ ((off >> 3) & 0x70);
        size_t g = (size_t)(q0 + row) * DH + ch * 8;
        *(uint4*)(smc + AT_QH + sw) = *(const uint4*)(Qh + g);
        *(uint4*)(smc + AT_QL + sw) = *(const uint4*)(Ql + g);
    }
#pragma unroll
    for (int it = 0; it < 4; it++) {
        *(uint4*)(smc + AT_KH + ksw[it]) = *(const uint4*)(Kh + kgo[it]);
        *(uint4*)(smc + AT_KL + ksw[it]) = *(const uint4*)(Kl + kgo[it]);
    }
    __syncthreads();

    const uint64_t dQh = make_desc(sb + AT_QH);
    const uint64_t dQl = make_desc(sb + AT_QL);
    const uint64_t dKh = make_desc(sb + AT_KH);
    const uint64_t dKl = make_desc(sb + AT_KL);
    const uint64_t dVh = make_desc(sb + AT_VH);
    const uint64_t dVl = make_desc(sb + AT_VL);
    const uint64_t dPh = make_desc(sb + AT_PH);
    const uint64_t dPl = make_desc(sb + AT_PL);

    // Issue S(0)
    if (tid == 0) {
        FENCE_ASYNC();
#pragma unroll
        for (int s = 0; s < 8; s++) {
            uint64_t oa = (s < 4) ? (uint64_t)(s * 2) : (uint64_t)(1024 + (s - 4) * 2);
            uint64_t ob = (s < 4) ? (uint64_t)(s * 2) : (uint64_t)(512 + (s - 4) * 2);
            mma_f16_ss(tmem + TM_S, dQh + oa, dKh + ob, IDESC_N64, s != 0);
            mma_f16_ss(tmem + TM_S, dQh + oa, dKl + ob, IDESC_N64, 1u);
            mma_f16_ss(tmem + TM_S, dQl + oa, dKh + ob, IDESC_N64, 1u);
        }
        TC_COMMIT(sb + 8);
    }

    // Prefetch K(1) and V(0) into registers
    uint4 kbh[4], kbl[4], vbh[4], vbl[4];
#pragma unroll
    for (int it = 0; it < 4; it++) {
        kbh[it] = *(const uint4*)(Kh + (size_t)64 * DH + kgo[it]);
        kbl[it] = *(const uint4*)(Kl + (size_t)64 * DH + kgo[it]);
        vbh[it] = *(const uint4*)(Vh + vgo[it]);
        vbl[it] = *(const uint4*)(Vl + vgo[it]);
    }

    float lacc = 0.0f;
    const float scl2 = scale * 1.4426950408889634f;   // fold scale into log2e

    for (int t = 0; t < 32; t++) {
        // 1. wait S(t)
        MBAR_WAIT(sb + 8, t & 1);
        TC_FENCE_AFTER();

        // 2. store K(t+1), issue S(t+1) into the other S buffer
        if (t < 31) {
#pragma unroll
            for (int it = 0; it < 4; it++) {
                *(uint4*)(smc + AT_KH + ksw[it]) = kbh[it];
                *(uint4*)(smc + AT_KL + ksw[it]) = kbl[it];
            }
        }
        __syncthreads();
        if (t < 31 && tid == 0) {
            FENCE_ASYNC();
            uint32_t sbuf = tmem + TM_S + ((t + 1) & 1) * 64;
#pragma unroll
            for (int s = 0; s < 8; s++) {
                uint64_t oa = (s < 4) ? (uint64_t)(s * 2) : (uint64_t)(1024 + (s - 4) * 2);
                uint64_t ob = (s < 4) ? (uint64_t)(s * 2) : (uint64_t)(512 + (s - 4) * 2);
                mma_f16_ss(sbuf, dQh + oa, dKh + ob, IDESC_N64, s != 0);
                mma_f16_ss(sbuf, dQh + oa, dKl + ob, IDESC_N64, 1u);
                mma_f16_ss(sbuf, dQl + oa, dKh + ob, IDESC_N64, 1u);
            }
            TC_COMMIT(sb + 8);
        }

        // 3. prefetch K(t+2)
        if (t < 30) {
            size_t kadd = (size_t)((t + 2) << 6) * DH;
#pragma unroll
            for (int it = 0; it < 4; it++) {
                kbh[it] = *(const uint4*)(Kh + kadd + kgo[it]);
                kbl[it] = *(const uint4*)(Kl + kadd + kgo[it]);
            }
        }

        // 4. softmax(t): LDTM S, fast exp (fma pipe) with prefetched maskT regs
        float pv0[32];
        {
            uint32_t dr[32];
            TC_LD_X32(dr, tmem + TM_S + (t & 1) * 64 + coff);
            TC_WAIT_LD();
#pragma unroll
            for (int c = 0; c < 32; c += 2) {
                float t0 = fmaf(__uint_as_float(dr[c]),     scl2, mreg[c]);
                float t1 = fmaf(__uint_as_float(dr[c + 1]), scl2, mreg[c + 1]);
                float z0 = t0 + 12582912.0f, z1 = t1 + 12582912.0f;
                float f0 = t0 - (z0 - 12582912.0f);
                float f1 = t1 - (z1 - 12582912.0f);
                float p0 = 1.3333558146e-3f, p1 = 1.3333558146e-3f;
                p0 = fmaf(p0, f0, 9.6181291076e-3f); p1 = fmaf(p1, f1, 9.6181291076e-3f);
                p0 = fmaf(p0, f0, 5.5504108664e-2f); p1 = fmaf(p1, f1, 5.5504108664e-2f);
                p0 = fmaf(p0, f0, 2.4022650696e-1f); p1 = fmaf(p1, f1, 2.4022650696e-1f);
                p0 = fmaf(p0, f0, 6.9314718056e-1f); p1 = fmaf(p1, f1, 6.9314718056e-1f);
                p0 = fmaf(p0, f0, 1.0f);             p1 = fmaf(p1, f1, 1.0f);
                p0 = __int_as_float(__float_as_int(p0) + (__float_as_int(z0) << 23));
                p1 = __int_as_float(__float_as_int(p1) + (__float_as_int(z1) << 23));
                pv0[c] = p0; pv0[c + 1] = p1;
                lacc += p0 + p1;
            }
        }

        // 5. wait PV(t-1) before overwriting V/P SMEM
        if (t > 0) MBAR_WAIT(sb + 16, (t - 1) & 1);

        // 6. store V(t) (from regs) + P(t) (truncation split + PRMT pack)
#pragma unroll
        for (int it = 0; it < 4; it++) {
            *(uint4*)(smc + AT_VH + vsw[it]) = vbh[it];
            *(uint4*)(smc + AT_VL + vsw[it]) = vbl[it];
        }
#pragma unroll
        for (int c = 0; c < 32; c += 2) {
            float p0 = pv0[c], p1 = pv0[c + 1];
            uint32_t b0 = __float_as_int(p0), b1 = __float_as_int(p1);
            uint32_t hp = __byte_perm(b0, b1, 0x7632);            // bf16 pair (truncated)
            float h0 = __int_as_float(b0 & 0xFFFF0000u);
            float h1 = __int_as_float(b1 & 0xFFFF0000u);
            __nv_bfloat162 lo2 = __floats2bfloat162_rn(p0 - h0, p1 - h1);
            uint32_t off = qrow * 128 + (coff + c) * 2;
            uint32_t sw = off ^ ((off >> 3) & 0x70);
            *(uint32_t*)(smc + AT_PH + sw) = hp;
            *(uint32_t*)(smc + AT_PL + sw) = *(uint32_t*)&lo2;
        }
        __syncthreads();

        // 7. issue PV(t)
        if (tid == 0) {
            FENCE_ASYNC();
#pragma unroll
            for (int s = 0; s < 4; s++) {
                uint64_t o2 = (uint64_t)(s * 2);
                mma_f16_ss(tmem + TM_O, dPh + o2, dVh + o2, IDESC_N128, !(t == 0 && s == 0));
                mma_f16_ss(tmem + TM_O, dPh + o2, dVl + o2, IDESC_N128, 1u);
                mma_f16_ss(tmem + TM_O, dPl + o2, dVh + o2, IDESC_N128, 1u);
            }
            TC_COMMIT(sb + 16);
        }

        // 8. prefetch V(t+1) and maskT(t+1)
        if (t < 31) {
            size_t vadd = (size_t)((t + 1) << 6);
#pragma unroll
            for (int it = 0; it < 4; it++) {
                vbh[it] = *(const uint4*)(Vh + vadd + vgo[it]);
                vbl[it] = *(const uint4*)(Vl + vadd + vgo[it]);
            }
            const float* mTt = mTb + (size_t)((t + 1) << 6) * SS;
#pragma unroll
            for (int c = 0; c < 32; c++)
                mreg[c] = mTt[(size_t)(coff + c) * SS];
        }
    }

    MBAR_WAIT(sb + 16, 31 & 1);
    TC_FENCE_AFTER();

    // combine l halves
    l_sm[half * 128 + qrow] = lacc;
    __syncthreads();
    float inv = 1.0f / (l_sm[qrow] + l_sm[128 + qrow]);

    // write ctx (rows qrow, d cols half*64..+63) as bf16 hi/lo
    {
        uint32_t d0[32], d1[32];
        TC_LD_X32(d0, tmem + TM_O + half * 64);
        TC_LD_X32(d1, tmem + TM_O + half * 64 + 32);
        TC_WAIT_LD();
        size_t base = ((size_t)b * SS + q0 + qrow) * DM + h * DH + half * 64;
#pragma unroll
        for (int j = 0; j < 64; j += 2) {
            float v0 = __uint_as_float(j < 32 ? d0[j]     : d1[j - 32]) * inv;
            float v1 = __uint_as_float(j < 31 ? d0[j + 1] : d1[j + 1 - 32]) * inv;
            __nv_bfloat16 h0 = __float2bfloat16(v0);
            __nv_bfloat16 h1 = __float2bfloat16(v1);
            __nv_bfloat16 l0 = __float2bfloat16(v0 - __bfloat162float(h0));
            __nv_bfloat16 l1 = __float2bfloat16(v1 - __bfloat162float(h1));
            __nv_bfloat16 hp[2] = {h0, h1}, lp[2] = {l0, l1};
            *(uint32_t*)(g_Ch + base + j) = *(uint32_t*)hp;
            *(uint32_t*)(g_Cl + base + j) = *(uint32_t*)lp;
        }
    }
    __syncthreads();
    if (wid == 0) TC_DEALLOC(tmem, 256);

#else
    // ---------------- SIMT fp32 fallback (two 64-row halves) ----------------
    float* sm = (float*)smc;
    float* Qs = sm;
    float* Ks = Qs + 64 * QS_LD;
    float* Vs = Ks + 64 * QS_LD;
    float* Pt = Vs + 64 * 128;

    const int ty = tid >> 4;
    const int tx = tid & 15;
    const size_t headoff = (size_t)(b * NH + h) * SS * DH;
    const float* __restrict__ Qg = g_Q + headoff;
    const float* __restrict__ Kg = g_K + headoff;
    const float* __restrict__ Vg = g_V + headoff;

    for (int qh = 0; qh < 2; qh++) {
        const int q0 = (blockIdx.x << 7) + (qh << 6);
        __syncthreads();
#pragma unroll
        for (int it = 0; it < 8; it++) {
            int idx = tid + it * 256;
            int row = idx >> 5;
            int d4  = (idx & 31) << 2;
            *(float4*)&Qs[row * QS_LD + d4] =
                *(const float4*)(Qg + (size_t)(q0 + row) * DH + d4);
        }

        const int r0 = ty * 4;
        float m_i[4], l_i[4], acc[4][8];
#pragma unroll
        for (int i = 0; i < 4; i++) {
            m_i[i] = -1e30f;
            l_i[i] = 0.0f;
#pragma unroll
            for (int j = 0; j < 8; j++) acc[i][j] = 0.0f;
        }

        for (int kv0 = 0; kv0 < SS; kv0 += 64) {
            __syncthreads();
#pragma unroll
            for (int it = 0; it < 8; it++) {
                int idx = tid + it * 256;
                int row = idx >> 5;
                int d4  = (idx & 31) << 2;
                *(float4*)&Ks[row * QS_LD + d4] =
                    *(const float4*)(Kg + (size_t)(kv0 + row) * DH + d4);
                *(float4*)&Vs[row * 128 + d4] =
                    *(const float4*)(Vg + (size_t)(kv0 + row) * DH + d4);
            }
            __syncthreads();

            float s[4][4];
#pragma unroll
            for (int i = 0; i < 4; i++)
#pragma unroll
                for (int j = 0; j < 4; j++) s[i][j] = 0.0f;

#pragma unroll 8
            for (int d = 0; d < DH; d += 4) {
                float4 q[4], k[4];
#pragma unroll
                for (int i = 0; i < 4; i++) q[i] = *(float4*)&Qs[(r0 + i) * QS_LD + d];
#pragma unroll
                for (int j = 0; j < 4; j++) k[j] = *(float4*)&Ks[(tx + 16 * j) * QS_LD + d];
#pragma unroll
                for (int i = 0; i < 4; i++)
#pragma unroll
                    for (int j = 0; j < 4; j++)
                        s[i][j] += q[i].x * k[j].x + q[i].y * k[j].y +
                                   q[i].z * k[j].z + q[i].w * k[j].w;
            }

#pragma unroll
            for (int i = 0; i < 4; i++) {
                const float* mrow = mask + (size_t)(q0 + r0 + i) * SS + kv0;
#pragma unroll
                for (int j = 0; j < 4; j++)
                    s[i][j] = s[i][j] * scale + mrow[tx + 16 * j];

                float mx = fmaxf(fmaxf(s[i][0], s[i][1]), fmaxf(s[i][2], s[i][3]));
#pragma unroll
                for (int o = 1; o < 16; o <<= 1)
                    mx = fmaxf(mx, __shfl_xor_sync(0xffffffffu, mx, o));
                float mnew = fmaxf(m_i[i], mx);

                float sum = 0.0f;
#pragma unroll
                for (int j = 0; j < 4; j++) {
                    s[i][j] = __expf(s[i][j] - mnew);
                    sum += s[i][j];
                }
#pragma unroll
                for (int o = 1; o < 16; o <<= 1)
                    sum += __shfl_xor_sync(0xffffffffu, sum, o);

                float alpha = __expf(m_i[i] - mnew);
                l_i[i] = l_i[i] * alpha + sum;
                m_i[i] = mnew;
#pragma unroll
                for (int j = 0; j < 8; j++) acc[i][j] *= alpha;
            }

#pragma unroll
            for (int j = 0; j < 4; j++)
#pragma unroll
                for (int i = 0; i < 4; i++)
                    Pt[(tx + 16 * j) * PT_LD + r0 + i] = s[i][j];
            __syncthreads();

#pragma unroll 8
            for (int c = 0; c < 64; c++) {
                float4 p  = *(float4*)&Pt[c * PT_LD + r0];
                float4 v0 = *(float4*)&Vs[c * 128 + tx * 8];
                float4 v1 = *(float4*)&Vs[c * 128 + tx * 8 + 4];
                float pa[4] = {p.x, p.y, p.z, p.w};
                float va[8] = {v0.x, v0.y, v0.z, v0.w, v1.x, v1.y, v1.z, v1.w};
#pragma unroll
                for (int i = 0; i < 4; i++)
#pragma unroll
                    for (int j = 0; j < 8; j++)
                        acc[i][j] += pa[i] * va[j];
            }
        }

#pragma unroll
        for (int i = 0; i < 4; i++) {
            float inv = 1.0f / l_i[i];
            size_t base = ((size_t)b * SS + q0 + r0 + i) * DM + h * DH + tx * 8;
            __nv_bfloat16 hh[8], ll[8];
#pragma unroll
            for (int j = 0; j < 8; j++) {
                float v = acc[i][j] * inv;
                hh[j] = __float2bfloat16(v);
                ll[j] = __float2bfloat16(v - __bfloat162float(hh[j]));
            }
            *(uint4*)&g_Ch[base] = *(uint4*)hh;
            *(uint4*)&g_Cl[base] = *(uint4*)ll;
        }
    }
#endif
}

// ---------------------------------------------------------------------------
extern "C" void kernel_launch(void* const* d_in, const int* in_sizes, int n_in,
                              void* d_out, int out_size)
{
    const float* x    = (const float*)d_in[0];
    const float* mask = (const float*)d_in[1];
    const float* wq   = (const float*)d_in[2];
    const float* bq   = (const float*)d_in[3];
    const float* wk   = (const float*)d_in[4];
    const float* bk   = (const float*)d_in[5];
    const float* wv   = (const float*)d_in[6];
    const float* bv   = (const float*)d_in[7];
    const float* wo   = (const float*)d_in[8];
    const float* bo   = (const float*)d_in[9];
    float* out = (float*)d_out;

    cudaFuncSetAttribute(tc_gemm, cudaFuncAttributeMaxDynamicSharedMemorySize, GEMM_SMEM);
    cudaFuncSetAttribute(attn_kernel, cudaFuncAttributeMaxDynamicSharedMemorySize, ATT_SMEM);

    split_x_kernel<<<(MT * DM) / (256 * 4), 256>>>(x);
    wsplit_kernel<<<dim3(64, 64, 4), 256>>>(wq, wk, wv, wo);
    mtrans_kernel<<<dim3(SS / 32, SS / 32), 256>>>(mask);

    // QKV projections (BM=256 per CTA)
    tc_gemm<<<dim3(16, 16, 3), 256, GEMM_SMEM>>>(bq, bk, bv, nullptr, 0, 1);

    // attention
    const float scale = 0.08838834764831845f;  // 1/sqrt(128)
    attn_kernel<<<dim3(SS / 128, NH, BB), 256, ATT_SMEM>>>(mask, scale);

    // output projection (BM=256 per CTA)
    tc_gemm<<<dim3(16, 16, 1), 256, GEMM_SMEM>>>(bo, bo, bo, out, 3, 0);
}

// round 14
// speedup vs baseline: 1.3067x; 1.0108x over previous
#include <cuda_runtime.h>
#include <cuda_bf16.h>
#include <cstdint>

#define DM 2048
#define NH 16
#define DH 128
#define BB 2
#define SS 2048
#define MT (BB*SS)   // 4096 rows

// ---------------------------------------------------------------------------
// Device scratch (allocation-free per harness rules)
// ---------------------------------------------------------------------------
__device__ float g_Q[(size_t)MT*DM];                 // fp32 (fallback path only)
__device__ float g_K[(size_t)MT*DM];
__device__ float g_V[(size_t)MT*DM];
__device__ float g_maskT[(size_t)SS*SS];             // mask^T * log2e
__device__ __nv_bfloat16 g_Qh[(size_t)MT*DM];        // [B,H,S,d] splits (a-path)
__device__ __nv_bfloat16 g_Ql[(size_t)MT*DM];
__device__ __nv_bfloat16 g_Kh[(size_t)MT*DM];
__device__ __nv_bfloat16 g_Kl[(size_t)MT*DM];
__device__ __nv_bfloat16 g_Vth[(size_t)MT*DM];       // V^T [B,H,d,S]
__device__ __nv_bfloat16 g_Vtl[(size_t)MT*DM];
__device__ __nv_bfloat16 g_Xh[(size_t)MT*DM];        // x split  [M,K]
__device__ __nv_bfloat16 g_Xl[(size_t)MT*DM];
__device__ __nv_bfloat16 g_Ch[(size_t)MT*DM];        // attention ctx split [M,K]
__device__ __nv_bfloat16 g_Cl[(size_t)MT*DM];
__device__ __nv_bfloat16 g_Wh[(size_t)4*DM*DM];      // transposed weights [N,K], z: q,k,v,o
__device__ __nv_bfloat16 g_Wl[(size_t)4*DM*DM];

// ---------------------------------------------------------------------------
// tcgen05 helpers — only in the sm_103a feature pass; plain sm_103 pass gets
// SIMT fallback bodies so both ptxas passes compile.
// ---------------------------------------------------------------------------
__device__ __forceinline__ uint32_t smem_u32(const void* p) {
    uint32_t a;
    asm("{ .reg .u64 t; cvta.to.shared.u64 t, %1; cvt.u32.u64 %0, t; }" : "=r"(a) : "l"(p));
    return a;
}

#if defined(__CUDA_ARCH_FEAT_SM103_ALL)

#define TC_ALLOC(sm, n)  asm volatile("tcgen05.alloc.cta_group::1.sync.aligned.shared::cta.b32 [%0], %1;" :: "r"(sm), "r"(n) : "memory")
#define TC_RELINQ()      asm volatile("tcgen05.relinquish_alloc_permit.cta_group::1.sync.aligned;")
#define TC_DEALLOC(t, n) asm volatile("tcgen05.dealloc.cta_group::1.sync.aligned.b32 %0, %1;" :: "r"(t), "r"(n))
#define TC_COMMIT(mb)    asm volatile("tcgen05.commit.cta_group::1.mbarrier::arrive::one.shared::cluster.b64 [%0];" :: "r"(mb) : "memory")
#define TC_FENCE_AFTER() asm volatile("tcgen05.fence::after_thread_sync;" ::: "memory")
#define TC_WAIT_LD()     asm volatile("tcgen05.wait::ld.sync.aligned;" ::: "memory")
#define MBAR_INIT(mb, c) asm volatile("mbarrier.init.shared.b64 [%0], %1;" :: "r"(mb), "r"(c) : "memory")
#define FENCE_ASYNC()    asm volatile("fence.proxy.async.shared::cta;" ::: "memory")

#define MBAR_WAIT(mb, ph) do {                                                   \
    uint32_t _m = (mb), _p = (ph), _d;                                           \
    asm volatile("{\n\t.reg .pred p;\n\t"                                        \
        "mbarrier.try_wait.parity.acquire.cta.shared::cta.b64 p, [%1], %2;\n\t"  \
        "selp.b32 %0, 1, 0, p;\n\t}"                                             \
        : "=r"(_d) : "r"(_m), "r"(_p) : "memory");                               \
    if (!_d) {                                                                   \
        asm volatile("{\n\t.reg .pred P1;\n\t"                                   \
        "WL_%=:\n\t"                                                             \
        "mbarrier.try_wait.parity.acquire.cta.shared::cta.b64 P1, [%0], %1, 0x989680;\n\t" \
        "@P1 bra.uni WD_%=;\n\t"                                                 \
        "bra.uni WL_%=;\n\t"                                                     \
        "WD_%=:\n\t}" :: "r"(_m), "r"(_p) : "memory");                           \
    }                                                                            \
} while (0)

#define TC_LD_X32(r, ta)                                                         \
    asm volatile("tcgen05.ld.sync.aligned.32x32b.x32.b32 "                       \
        "{%0, %1, %2, %3, %4, %5, %6, %7, "                                      \
        " %8, %9, %10, %11, %12, %13, %14, %15, "                                \
        " %16, %17, %18, %19, %20, %21, %22, %23, "                              \
        " %24, %25, %26, %27, %28, %29, %30, %31}, [%32];"                       \
        : "=r"((r)[0]), "=r"((r)[1]), "=r"((r)[2]), "=r"((r)[3]),                \
          "=r"((r)[4]), "=r"((r)[5]), "=r"((r)[6]), "=r"((r)[7]),                \
          "=r"((r)[8]), "=r"((r)[9]), "=r"((r)[10]), "=r"((r)[11]),              \
          "=r"((r)[12]), "=r"((r)[13]), "=r"((r)[14]), "=r"((r)[15]),            \
          "=r"((r)[16]), "=r"((r)[17]), "=r"((r)[18]), "=r"((r)[19]),            \
          "=r"((r)[20]), "=r"((r)[21]), "=r"((r)[22]), "=r"((r)[23]),            \
          "=r"((r)[24]), "=r"((r)[25]), "=r"((r)[26]), "=r"((r)[27]),            \
          "=r"((r)[28]), "=r"((r)[29]), "=r"((r)[30]), "=r"((r)[31])             \
        : "r"(ta))

// SW128 K-major SMEM descriptor (layout=2, version=1, SBO=64, LBO=1)
static __device__ __forceinline__ uint64_t make_desc(uint32_t addr) {
    const uint64_t base =
        (uint64_t(2) << 61) | (uint64_t(1) << 46) | (uint64_t(64) << 32) | (uint64_t(1) << 16);
    return base | ((uint64_t)(addr >> 4) & 0x3FFF);
}

// idesc: dtype=F32, atype=btype=BF16, M=128, N variable
#define IDESC_N128 ((1u<<4) | (1u<<7) | (1u<<10) | ((128u/8)<<17) | ((128u/16)<<24))
#define IDESC_N64  ((1u<<4) | (1u<<7) | (1u<<10) | ((64u/8)<<17)  | ((128u/16)<<24))

__device__ __forceinline__ void mma_f16_ss(uint32_t d, uint64_t a, uint64_t b,
                                           uint32_t idesc, uint32_t en) {
    asm volatile(
        "{\n\t.reg .pred p;\n\t"
        "setp.ne.u32 p, %4, 0;\n\t"
        "tcgen05.mma.cta_group::1.kind::f16 [%0], %1, %2, %3, {%5,%5,%5,%5}, p;\n\t}"
        :: "r"(d), "l"(a), "l"(b), "r"(idesc), "r"(en), "r"(0u) : "memory");
}

#endif  // __CUDA_ARCH_FEAT_SM103_ALL

// ---------------------------------------------------------------------------
// Prep 1: split x into bf16 hi/lo
// ---------------------------------------------------------------------------
__global__ void split_x_kernel(const float* __restrict__ x)
{
    size_t i = ((size_t)blockIdx.x * 256 + threadIdx.x) * 4;
    float4 v = *(const float4*)(x + i);
    __nv_bfloat16 h[4], l[4];
    float vv[4] = {v.x, v.y, v.z, v.w};
#pragma unroll
    for (int j = 0; j < 4; j++) {
        h[j] = __float2bfloat16(vv[j]);
        l[j] = __float2bfloat16(vv[j] - __bfloat162float(h[j]));
    }
    *(uint2*)&g_Xh[i] = *(uint2*)h;
    *(uint2*)&g_Xl[i] = *(uint2*)l;
}

// ---------------------------------------------------------------------------
// Prep 2: transpose + split weights. W[K,N] fp32 -> Wt[N,K] bf16 hi/lo.
// ---------------------------------------------------------------------------
__global__ void wsplit_kernel(const float* __restrict__ wq, const float* __restrict__ wk,
                              const float* __restrict__ wv, const float* __restrict__ wo)
{
    __shared__ float t[32][33];
    const int z = blockIdx.z;
    const float* __restrict__ W = (z == 0) ? wq : (z == 1) ? wk : (z == 2) ? wv : wo;
    const int n0 = blockIdx.x << 5;
    const int k0 = blockIdx.y << 5;
    const int tx = threadIdx.x & 31;
    const int ty = threadIdx.x >> 5;   // 0..7

#pragma unroll
    for (int r = ty; r < 32; r += 8)
        t[r][tx] = W[(size_t)(k0 + r) * DM + n0 + tx];
    __syncthreads();

    const size_t zoff = (size_t)z * DM * DM;
#pragma unroll
    for (int r = ty; r < 32; r += 8) {
        float v = t[tx][r];    // = W[k0+tx][n0+r]
        __nv_bfloat16 h = __float2bfloat16(v);
        float lo = v - __bfloat162float(h);
        size_t o = zoff + (size_t)(n0 + r) * DM + k0 + tx;
        g_Wh[o] = h;
        g_Wl[o] = __float2bfloat16(lo);
    }
}

// ---------------------------------------------------------------------------
// Prep 3: maskT[kv][q] = mask[q][kv] * log2e.
// ---------------------------------------------------------------------------
__global__ void mtrans_kernel(const float* __restrict__ mask)
{
    __shared__ float t[32][33];
    const int x0 = blockIdx.x << 5;     // kv tile
    const int y0 = blockIdx.y << 5;     // q tile
    const int tx = threadIdx.x & 31;
    const int ty = threadIdx.x >> 5;    // 0..7

#pragma unroll
    for (int r = ty; r < 32; r += 8)
        t[r][tx] = mask[(size_t)(y0 + r) * SS + x0 + tx];
    __syncthreads();
#pragma unroll
    for (int r = ty; r < 32; r += 8)
        g_maskT[(size_t)(x0 + r) * SS + y0 + tx] =
            t[tx][r] * 1.4426950408889634f;
}

// ---------------------------------------------------------------------------
// GEMM: BM=256, BN=256 per CTA. 8 source tiles (A0,A1,B0,B1 x hi/lo = 128KB),
// TMEM 512 cols = 4 output quadrants. 48 MMAs (3072 tensor cyc) amortize one
// serial wait+STS chain per iteration. R11-style register prefetch.
// Grid (N/256, M/256, z).
// ---------------------------------------------------------------------------
#define GK 64
#define SM_MBAR 8
#define SM_A    1024
#define SM_TILE 16384                     // 128*64*2B
#define GEMM_SMEM (1024 + 8*SM_TILE)      // 129 KB -> 1 CTA/SM

__global__ __launch_bounds__(256, 1) void tc_gemm(
    const float* __restrict__ b0, const float* __restrict__ b1, const float* __restrict__ b2,
    float* __restrict__ outp, int wsel, int split)
{
    extern __shared__ char smem[];
    const int tid = threadIdx.x;
    const int z   = blockIdx.z;
    const int m0  = blockIdx.y << 8;       // 256 rows
    const int n0  = blockIdx.x << 8;       // 256 cols
    const __nv_bfloat16* __restrict__ Abase_h = (split ? g_Xh : g_Ch);
    const __nv_bfloat16* __restrict__ Abase_l = (split ? g_Xl : g_Cl);
    const size_t wz = (size_t)(wsel + z) * DM * DM;
    const float* __restrict__ bias = (z == 0) ? b0 : (z == 1) ? b1 : b2;

    // 8 source tiles: A0h, A0l, A1h, A1l, B0h, B0l, B1h, B1l
    const __nv_bfloat16* __restrict__ tp[8] = {
        Abase_h + (size_t)m0 * DM,
        Abase_l + (size_t)m0 * DM,
        Abase_h + (size_t)(m0 + 128) * DM,
        Abase_l + (size_t)(m0 + 128) * DM,
        g_Wh + wz + (size_t)n0 * DM,
        g_Wl + wz + (size_t)n0 * DM,
        g_Wh + wz + (size_t)(n0 + 128) * DM,
        g_Wl + wz + (size_t)(n0 + 128) * DM
    };

#if defined(__CUDA_ARCH_FEAT_SM103_ALL)
    // ------------------------- tcgen05 path -------------------------
    const uint32_t sb = smem_u32(smem);
    const int wid = tid >> 5;

    if (wid == 0) {
        TC_ALLOC(sb, 512);
        TC_RELINQ();
    }
    if (tid == 0) MBAR_INIT(sb + SM_MBAR, 1);

    // per-thread tile addresses (4 chunks per tile)
    uint32_t tsw[4]; size_t tgo[4];
#pragma unroll
    for (int it = 0; it < 4; it++) {
        int idx = tid + it * 256;          // 0..1023
        int row = idx >> 3;                // 0..127
        int cc  = idx & 7;                 // 16B chunk
        uint32_t off = row * 128 + cc * 16;
        tsw[it] = off ^ ((off >> 3) & 0x70);
        tgo[it] = (size_t)row * DM + cc * 8;   // + k0
    }

    __syncthreads();
    uint32_t tmem;
    asm volatile("ld.shared.b32 %0, [%1];" : "=r"(tmem) : "r"(sb));

    uint64_t dt[8];
#pragma unroll
    for (int q = 0; q < 8; q++)
        dt[q] = make_desc(sb + SM_A + q * SM_TILE);

    const int NIT = DM / GK;               // 32
    for (int t = 0; t < NIT; t++) {
        const size_t k0 = (size_t)t * GK;

        // prefetch all 8 tiles into registers (overlaps in-flight MMA)
        uint4 rr[8][4];
#pragma unroll
        for (int q = 0; q < 8; q++)
#pragma unroll
            for (int it = 0; it < 4; it++)
                rr[q][it] = *(const uint4*)(tp[q] + tgo[it] + k0);

        // wait for MMA(t-1) to finish reading SMEM
        if (t > 0) MBAR_WAIT(sb + SM_MBAR, (t - 1) & 1);

#pragma unroll
        for (int q = 0; q < 8; q++)
#pragma unroll
            for (int it = 0; it < 4; it++)
                *(uint4*)(smem + SM_A + q * SM_TILE + tsw[it]) = rr[q][it];
        __syncthreads();

        if (tid == 0) {
            FENCE_ASYNC();
#pragma unroll
            for (int s = 0; s < 4; s++) {
                uint64_t oa = (uint64_t)(s * 2);
                uint32_t en0 = !(t == 0 && s == 0);
                // D00 (cols 0)   = A0 @ B0
                mma_f16_ss(tmem,       dt[0] + oa, dt[4] + oa, IDESC_N128, en0);
                mma_f16_ss(tmem,       dt[0] + oa, dt[5] + oa, IDESC_N128, 1u);
                mma_f16_ss(tmem,       dt[1] + oa, dt[4] + oa, IDESC_N128, 1u);
                // D10 (cols 128) = A1 @ B0
                mma_f16_ss(tmem + 128, dt[2] + oa, dt[4] + oa, IDESC_N128, en0);
                mma_f16_ss(tmem + 128, dt[2] + oa, dt[5] + oa, IDESC_N128, 1u);
                mma_f16_ss(tmem + 128, dt[3] + oa, dt[4] + oa, IDESC_N128, 1u);
                // D01 (cols 256) = A0 @ B1
                mma_f16_ss(tmem + 256, dt[0] + oa, dt[6] + oa, IDESC_N128, en0);
                mma_f16_ss(tmem + 256, dt[0] + oa, dt[7] + oa, IDESC_N128, 1u);
                mma_f16_ss(tmem + 256, dt[1] + oa, dt[6] + oa, IDESC_N128, 1u);
                // D11 (cols 384) = A1 @ B1
                mma_f16_ss(tmem + 384, dt[2] + oa, dt[6] + oa, IDESC_N128, en0);
                mma_f16_ss(tmem + 384, dt[2] + oa, dt[7] + oa, IDESC_N128, 1u);
                mma_f16_ss(tmem + 384, dt[3] + oa, dt[6] + oa, IDESC_N128, 1u);
            }
            TC_COMMIT(sb + SM_MBAR);
        }
    }
    MBAR_WAIT(sb + SM_MBAR, (NIT - 1) & 1);
    TC_FENCE_AFTER();

    // Epilogue: warps 0-3 -> m-half 0, warps 4-7 -> m-half 1; loop n-quadrants.
    {
        const int mh  = wid >> 2;
        const int w4  = wid & 3;
        const int lid = tid & 31;
        const int m = m0 + mh * 128 + w4 * 32 + lid;
        const int bb = m >> 11;
        const int s  = m & (SS - 1);
#pragma unroll
        for (int nq = 0; nq < 2; nq++) {
            const int ncol0 = n0 + nq * 128;
            const int h = ncol0 >> 7;
            const uint32_t tmq = tmem + mh * 128 + nq * 256;
#pragma unroll
            for (int cc = 0; cc < 4; cc++) {
                uint32_t dr[32];
                TC_LD_X32(dr, tmq + cc * 32);
                TC_WAIT_LD();
                int coff = cc * 32;
                if (!split) {
                    size_t base = (size_t)m * DM + ncol0 + coff;
#pragma unroll
                    for (int j = 0; j < 32; j += 4) {
                        float4 r;
                        r.x = __uint_as_float(dr[j + 0]) + bias[ncol0 + coff + j + 0];
                        r.y = __uint_as_float(dr[j + 1]) + bias[ncol0 + coff + j + 1];
                        r.z = __uint_as_float(dr[j + 2]) + bias[ncol0 + coff + j + 2];
                        r.w = __uint_as_float(dr[j + 3]) + bias[ncol0 + coff + j + 3];
                        *(float4*)(outp + base + j) = r;
                    }
                } else if (z == 2) {
                    // V^T: [B,H][d][S], d = coff+j (within head h)
                    size_t vbase = (size_t)(bb * NH + h) * DH * SS + s;
#pragma unroll
                    for (int j = 0; j < 32; j++) {
                        float v = __uint_as_float(dr[j]) + bias[ncol0 + coff + j];
                        __nv_bfloat16 hh = __float2bfloat16(v);
                        size_t o = vbase + (size_t)(coff + j) * SS;
                        g_Vth[o] = hh;
                        g_Vtl[o] = __float2bfloat16(v - __bfloat162float(hh));
                    }
                } else {
                    // Q/K: [B,H,S,d] bf16 splits, pair stores
                    __nv_bfloat16* __restrict__ oh = (z == 0) ? g_Qh : g_Kh;
                    __nv_bfloat16* __restrict__ ol = (z == 0) ? g_Ql : g_Kl;
                    size_t base = ((size_t)(bb * NH + h) * SS + s) * DH + coff;
#pragma unroll
                    for (int j = 0; j < 32; j += 2) {
                        float v0 = __uint_as_float(dr[j])     + bias[ncol0 + coff + j];
                        float v1 = __uint_as_float(dr[j + 1]) + bias[ncol0 + coff + j + 1];
                        __nv_bfloat16 h0 = __float2bfloat16(v0);
                        __nv_bfloat16 h1 = __float2bfloat16(v1);
                        __nv_bfloat16 l0 = __float2bfloat16(v0 - __bfloat162float(h0));
                        __nv_bfloat16 l1 = __float2bfloat16(v1 - __bfloat162float(h1));
                        __nv_bfloat16 hp[2] = {h0, h1}, lp[2] = {l0, l1};
                        *(uint32_t*)(oh + base + j) = *(uint32_t*)hp;
                        *(uint32_t*)(ol + base + j) = *(uint32_t*)lp;
                    }
                }
            }
        }
    }
    __syncthreads();
    if (wid == 0) TC_DEALLOC(tmem, 512);

#else
    // ------------------------- SIMT fallback (sm_103 pass) -------------------------
    float* As = (float*)smem;            // [16][132]
    float* Bs = As + 16 * 132;           // [16][128]
    const int ty = tid >> 4;
    const int tx = tid & 15;

    for (int mh = 0; mh < 2; mh++)
    for (int nq = 0; nq < 2; nq++) {
        const __nv_bfloat16* __restrict__ Ah = tp[mh * 2];
        const __nv_bfloat16* __restrict__ Al = tp[mh * 2 + 1];
        const __nv_bfloat16* __restrict__ Bh = tp[4 + nq * 2];
        const __nv_bfloat16* __restrict__ Bl = tp[5 + nq * 2];
        const int m0h   = m0 + mh * 128;
        const int ncol0 = n0 + nq * 128;

        float acc[8][8];
#pragma unroll
        for (int i = 0; i < 8; i++)
#pragma unroll
            for (int j = 0; j < 8; j++) acc[i][j] = 0.0f;

        __syncthreads();
        for (int k0 = 0; k0 < DM; k0 += 16) {
#pragma unroll
            for (int it = 0; it < 8; it++) {
                int idx = tid + it * 256;
                int row = idx >> 4;
                int kk  = idx & 15;
                As[kk * 132 + row] = __bfloat162float(Ah[(size_t)row * DM + k0 + kk]) +
                                     __bfloat162float(Al[(size_t)row * DM + k0 + kk]);
                Bs[kk * 128 + row] = __bfloat162float(Bh[(size_t)row * DM + k0 + kk]) +
                                     __bfloat162float(Bl[(size_t)row * DM + k0 + kk]);
            }
            __syncthreads();
#pragma unroll
            for (int k = 0; k < 16; k++) {
                float a[8], b[8];
                *(float4*)&a[0] = *(float4*)&As[k * 132 + ty * 8];
                *(float4*)&a[4] = *(float4*)&As[k * 132 + ty * 8 + 4];
                *(float4*)&b[0] = *(float4*)&Bs[k * 128 + tx * 8];
                *(float4*)&b[4] = *(float4*)&Bs[k * 128 + tx * 8 + 4];
#pragma unroll
                for (int i = 0; i < 8; i++)
#pragma unroll
                    for (int j = 0; j < 8; j++)
                        acc[i][j] += a[i] * b[j];
            }
            __syncthreads();
        }

        float bv[8];
#pragma unroll
        for (int j = 0; j < 8; j++) bv[j] = bias[ncol0 + tx * 8 + j];

#pragma unroll
        for (int i = 0; i < 8; i++) {
            int m = m0h + ty * 8 + i;
            float* __restrict__ obase;
            size_t base;
            if (split) {
                int h = ncol0 >> 7;
                int bb = m >> 11;
                int s  = m & (SS - 1);
                obase = (z == 0) ? g_Q : (z == 1) ? g_K : g_V;
                base = ((size_t)(bb * NH + h) * SS + s) * DH + tx * 8;
            } else {
                obase = outp;
                base = (size_t)m * DM + ncol0 + tx * 8;
            }
            float4 r0, r1;
            r0.x = acc[i][0] + bv[0]; r0.y = acc[i][1] + bv[1];
            r0.z = acc[i][2] + bv[2]; r0.w = acc[i][3] + bv[3];
            r1.x = acc[i][4] + bv[4]; r1.y = acc[i][5] + bv[5];
            r1.z = acc[i][6] + bv[6]; r1.w = acc[i][7] + bv[7];
            *(float4*)(obase + base)     = r0;
            *(float4*)(obase + base + 4) = r1;
        }
    }
#endif
}

// ---------------------------------------------------------------------------
// Attention. a-path: pipelined tcgen05 flash without max-subtraction.
// Grid (SS/128, NH, BB), 256 threads.  (Unchanged — known-good since R11.)
// ---------------------------------------------------------------------------
#define AT_LSM 128
#define AT_QH  2048
#define AT_QL  (AT_QH + 32768)
#define AT_KH  (AT_QL + 32768)
#define AT_KL  (AT_KH + 16384)
#define AT_VH  (AT_KL + 16384)
#define AT_VL  (AT_VH + 16384)
#define AT_PH  (AT_VL + 16384)
#define AT_PL  (AT_PH + 16384)
#define ATT_SMEM (AT_PL + 16384)          // 162 KB

#define TM_S 0        // two 64-col S buffers: 0 and 64
#define TM_O 128      // O accumulator: 128 cols

// SIMT fallback layout sizes
#define QS_LD 132
#define PT_LD 68

__global__ __launch_bounds__(256, 1) void attn_kernel(
    const float* __restrict__ mask, float scale)
{
    extern __shared__ char smc[];
    const int tid = threadIdx.x;
    const int h  = blockIdx.y;
    const int b  = blockIdx.z;

#if defined(__CUDA_ARCH_FEAT_SM103_ALL)
    const uint32_t sb = smem_u32(smc);
    const int wid  = tid >> 5;
    const int lane = tid & 31;
    const int sub  = wid & 3;            // TMEM subpartition
    const int half = wid >> 2;           // column half (0/1)
    const int q0   = blockIdx.x << 7;    // 128 q-rows
    const int qrow = sub * 32 + lane;

    const size_t hoff = (size_t)(b * NH + h) * SS * DH;
    const __nv_bfloat16* __restrict__ Qh = g_Qh + hoff;
    const __nv_bfloat16* __restrict__ Ql = g_Ql + hoff;
    const __nv_bfloat16* __restrict__ Kh = g_Kh + hoff;
    const __nv_bfloat16* __restrict__ Kl = g_Kl + hoff;
    const __nv_bfloat16* __restrict__ Vh = g_Vth + hoff;   // [d][S]
    const __nv_bfloat16* __restrict__ Vl = g_Vtl + hoff;
    float* l_sm = (float*)(smc + AT_LSM);

    if (wid == 0) {
        TC_ALLOC(sb, 256);
        TC_RELINQ();
    }
    if (tid == 0) { MBAR_INIT(sb + 8, 1); MBAR_INIT(sb + 16, 1); }

    // K-tile address helpers (per-thread 4 chunks)
    uint32_t ksw[4]; size_t kgo[4];
#pragma unroll
    for (int it = 0; it < 4; it++) {
        int idx = tid + it * 256;        // 0..1023
        int row = idx >> 4;              // 0..63
        int ch  = idx & 15;
        int acol = ch >> 3;
        uint32_t off = ((row >> 3) + acol * 8) * 1024 + (row & 7) * 128 + (ch & 7) * 16;
        ksw[it] = off ^ ((off >> 3) & 0x70);
        kgo[it] = (size_t)row * DH + ch * 8;     // + kv0*DH
    }
    // V-tile address helpers
    uint32_t vsw[4]; size_t vgo[4];
#pragma unroll
    for (int it = 0; it < 4; it++) {
        int idx = tid + it * 256;
        int row = idx >> 3;              // 0..127 (d)
        int ch  = idx & 7;
        uint32_t off = row * 128 + ch * 16;
        vsw[it] = off ^ ((off >> 3) & 0x70);
        vgo[it] = (size_t)row * SS + ch * 8;     // + kv0
    }

    __syncthreads();
    uint32_t tmem;
    asm volatile("ld.shared.b32 %0, [%1];" : "=r"(tmem) : "r"(sb));

    const int coff = half * 32;
    // maskT base for this thread's (column-lane) reads; lane-consecutive in q
    const float* __restrict__ mTb = g_maskT + q0 + qrow;

    // Prefetch maskT tile 0 (32 coalesced LDGs; latency hides behind Q load)
    float mreg[32];
#pragma unroll
    for (int c = 0; c < 32; c++)
        mreg[c] = mTb[(size_t)(coff + c) * SS];

    // Load Q tile [128,128] hi/lo (blocked-atom SW128) + K(0) directly to SMEM
#pragma unroll
    for (int it = 0; it < 8; it++) {
        int idx = tid + it * 256;        // 0..2047
        int row = idx >> 4;              // 0..127
        int ch  = idx & 15;
        int acol = ch >> 3;
        uint32_t off = ((row >> 3) + acol * 16) * 1024 + (row & 7) * 128 + (ch & 7) * 16;
        uint32_t sw = off ^ ((off >> 3) & 0x70);
        size_t g = (size_t)(q0 + row) * DH + ch * 8;
        *(uint4*)(smc + AT_QH + sw) = *(const uint4*)(Qh + g);
        *(uint4*)(smc + AT_QL + sw) = *(const uint4*)(Ql + g);
    }
#pragma unroll
    for (int it = 0; it < 4; it++) {
        *(uint4*)(smc + AT_KH + ksw[it]) = *(const uint4*)(Kh + kgo[it]);
        *(uint4*)(smc + AT_KL + ksw[it]) = *(const uint4*)(Kl + kgo[it]);
    }
    __syncthreads();

    const uint64_t dQh = make_desc(sb + AT_QH);
    const uint64_t dQl = make_desc(sb + AT_QL);
    const uint64_t dKh = make_desc(sb + AT_KH);
    const uint64_t dKl = make_desc(sb + AT_KL);
    const uint64_t dVh = make_desc(sb + AT_VH);
    const uint64_t dVl = make_desc(sb + AT_VL);
    const uint64_t dPh = make_desc(sb + AT_PH);
    const uint64_t dPl = make_desc(sb + AT_PL);

    // Issue S(0)
    if (tid == 0) {
        FENCE_ASYNC();
#pragma unroll
        for (int s = 0; s < 8; s++) {
            uint64_t oa = (s < 4) ? (uint64_t)(s * 2) : (uint64_t)(1024 + (s - 4) * 2);
            uint64_t ob = (s < 4) ? (uint64_t)(s * 2) : (uint64_t)(512 + (s - 4) * 2);
            mma_f16_ss(tmem + TM_S, dQh + oa, dKh + ob, IDESC_N64, s != 0);
            mma_f16_ss(tmem + TM_S, dQh + oa, dKl + ob, IDESC_N64, 1u);
            mma_f16_ss(tmem + TM_S, dQl + oa, dKh + ob, IDESC_N64, 1u);
        }
        TC_COMMIT(sb + 8);
    }

    // Prefetch K(1) and V(0) into registers
    uint4 kbh[4], kbl[4], vbh[4], vbl[4];
#pragma unroll
    for (int it = 0; it < 4; it++) {
        kbh[it] = *(const uint4*)(Kh + (size_t)64 * DH + kgo[it]);
        kbl[it] = *(const uint4*)(Kl + (size_t)64 * DH + kgo[it]);
        vbh[it] = *(const uint4*)(Vh + vgo[it]);
        vbl[it] = *(const uint4*)(Vl + vgo[it]);
    }

    float lacc = 0.0f;
    const float scl2 = scale * 1.4426950408889634f;   // fold scale into log2e

    for (int t = 0; t < 32; t++) {
        // 1. wait S(t)
        MBAR_WAIT(sb + 8, t & 1);
        TC_FENCE_AFTER();

        // 2. store K(t+1), issue S(t+1) into the other S buffer
        if (t < 31) {
#pragma unroll
            for (int it = 0; it < 4; it++) {
                *(uint4*)(smc + AT_KH + ksw[it]) = kbh[it];
                *(uint4*)(smc + AT_KL + ksw[it]) = kbl[it];
            }
        }
        __syncthreads();
        if (t < 31 && tid == 0) {
            FENCE_ASYNC();
            uint32_t sbuf = tmem + TM_S + ((t + 1) & 1) * 64;
#pragma unroll
            for (int s = 0; s < 8; s++) {
                uint64_t oa = (s < 4) ? (uint64_t)(s * 2) : (uint64_t)(1024 + (s - 4) * 2);
                uint64_t ob = (s < 4) ? (uint64_t)(s * 2) : (uint64_t)(512 + (s - 4) * 2);
                mma_f16_ss(sbuf, dQh + oa, dKh + ob, IDESC_N64, s != 0);
                mma_f16_ss(sbuf, dQh + oa, dKl + ob, IDESC_N64, 1u);
                mma_f16_ss(sbuf, dQl + oa, dKh + ob, IDESC_N64, 1u);
            }
            TC_COMMIT(sb + 8);
        }

        // 3. prefetch K(t+2)
        if (t < 30) {
            size_t kadd = (size_t)((t + 2) << 6) * DH;
#pragma unroll
            for (int it = 0; it < 4; it++) {
                kbh[it] = *(const uint4*)(Kh + kadd + kgo[it]);
                kbl[it] = *(const uint4*)(Kl + kadd + kgo[it]);
            }
        }

        // 4. softmax(t): LDTM S, fast exp (fma pipe) with prefetched maskT regs
        float pv0[32];
        {
            uint32_t dr[32];
            TC_LD_X32(dr, tmem + TM_S + (t & 1) * 64 + coff);
            TC_WAIT_LD();
#pragma unroll
            for (int c = 0; c < 32; c += 2) {
                float t0 = fmaf(__uint_as_float(dr[c]),     scl2, mreg[c]);
                float t1 = fmaf(__uint_as_float(dr[c + 1]), scl2, mreg[c + 1]);
                float z0 = t0 + 12582912.0f, z1 = t1 + 12582912.0f;
                float f0 = t0 - (z0 - 12582912.0f);
                float f1 = t1 - (z1 - 12582912.0f);
                float p0 = 1.3333558146e-3f, p1 = 1.3333558146e-3f;
                p0 = fmaf(p0, f0, 9.6181291076e-3f); p1 = fmaf(p1, f1, 9.6181291076e-3f);
                p0 = fmaf(p0, f0, 5.5504108664e-2f); p1 = fmaf(p1, f1, 5.5504108664e-2f);
                p0 = fmaf(p0, f0, 2.4022650696e-1f); p1 = fmaf(p1, f1, 2.4022650696e-1f);
                p0 = fmaf(p0, f0, 6.9314718056e-1f); p1 = fmaf(p1, f1, 6.9314718056e-1f);
                p0 = fmaf(p0, f0, 1.0f);             p1 = fmaf(p1, f1, 1.0f);
                p0 = __int_as_float(__float_as_int(p0) + (__float_as_int(z0) << 23));
                p1 = __int_as_float(__float_as_int(p1) + (__float_as_int(z1) << 23));
                pv0[c] = p0; pv0[c + 1] = p1;
                lacc += p0 + p1;
            }
        }

        // 5. wait PV(t-1) before overwriting V/P SMEM
        if (t > 0) MBAR_WAIT(sb + 16, (t - 1) & 1);

        // 6. store V(t) (from regs) + P(t) (truncation split + PRMT pack)
#pragma unroll
        for (int it = 0; it < 4; it++) {
            *(uint4*)(smc + AT_VH + vsw[it]) = vbh[it];
            *(uint4*)(smc + AT_VL + vsw[it]) = vbl[it];
        }
#pragma unroll
        for (int c = 0; c < 32; c += 2) {
            float p0 = pv0[c], p1 = pv0[c + 1];
            uint32_t b0 = __float_as_int(p0), b1 = __float_as_int(p1);
            uint32_t hp = __byte_perm(b0, b1, 0x7632);            // bf16 pair (truncated)
            float h0 = __int_as_float(b0 & 0xFFFF0000u);
            float h1 = __int_as_float(b1 & 0xFFFF0000u);
            __nv_bfloat162 lo2 = __floats2bfloat162_rn(p0 - h0, p1 - h1);
            uint32_t off = qrow * 128 + (coff + c) * 2;
            uint32_t sw = off ^ ((off >> 3) & 0x70);
            *(uint32_t*)(smc + AT_PH + sw) = hp;
            *(uint32_t*)(smc + AT_PL + sw) = *(uint32_t*)&lo2;
        }
        __syncthreads();

        // 7. issue PV(t)
        if (tid == 0) {
            FENCE_ASYNC();
#pragma unroll
            for (int s = 0; s < 4; s++) {
                uint64_t o2 = (uint64_t)(s * 2);
                mma_f16_ss(tmem + TM_O, dPh + o2, dVh + o2, IDESC_N128, !(t == 0 && s == 0));
                mma_f16_ss(tmem + TM_O, dPh + o2, dVl + o2, IDESC_N128, 1u);
                mma_f16_ss(tmem + TM_O, dPl + o2, dVh + o2, IDESC_N128, 1u);
            }
            TC_COMMIT(sb + 16);
        }

        // 8. prefetch V(t+1) and maskT(t+1)
        if (t < 31) {
            size_t vadd = (size_t)((t + 1) << 6);
#pragma unroll
            for (int it = 0; it < 4; it++) {
                vbh[it] = *(const uint4*)(Vh + vadd + vgo[it]);
                vbl[it] = *(const uint4*)(Vl + vadd + vgo[it]);
            }
            const float* mTt = mTb + (size_t)((t + 1) << 6) * SS;
#pragma unroll
            for (int c = 0; c < 32; c++)
                mreg[c] = mTt[(size_t)(coff + c) * SS];
        }
    }

    MBAR_WAIT(sb + 16, 31 & 1);
    TC_FENCE_AFTER();

    // combine l halves
    l_sm[half * 128 + qrow] = lacc;
    __syncthreads();
    float inv = 1.0f / (l_sm[qrow] + l_sm[128 + qrow]);

    // write ctx (rows qrow, d cols half*64..+63) as bf16 hi/lo
    {
        uint32_t d0[32], d1[32];
        TC_LD_X32(d0, tmem + TM_O + half * 64);
        TC_LD_X32(d1, tmem + TM_O + half * 64 + 32);
        TC_WAIT_LD();
        size_t base = ((size_t)b * SS + q0 + qrow) * DM + h * DH + half * 64;
#pragma unroll
        for (int j = 0; j < 64; j += 2) {
            float v0 = __uint_as_float(j < 32 ? d0[j]     : d1[j - 32]) * inv;
            float v1 = __uint_as_float(j < 31 ? d0[j + 1] : d1[j + 1 - 32]) * inv;
            __nv_bfloat16 h0 = __float2bfloat16(v0);
            __nv_bfloat16 h1 = __float2bfloat16(v1);
            __nv_bfloat16 l0 = __float2bfloat16(v0 - __bfloat162float(h0));
            __nv_bfloat16 l1 = __float2bfloat16(v1 - __bfloat162float(h1));
            __nv_bfloat16 hp[2] = {h0, h1}, lp[2] = {l0, l1};
            *(uint32_t*)(g_Ch + base + j) = *(uint32_t*)hp;
            *(uint32_t*)(g_Cl + base + j) = *(uint32_t*)lp;
        }
    }
    __syncthreads();
    if (wid == 0) TC_DEALLOC(tmem, 256);

#else
    // ---------------- SIMT fp32 fallback (two 64-row halves) ----------------
    float* sm = (float*)smc;
    float* Qs = sm;
    float* Ks = Qs + 64 * QS_LD;
    float* Vs = Ks + 64 * QS_LD;
    float* Pt = Vs + 64 * 128;

    const int ty = tid >> 4;
    const int tx = tid & 15;
    const size_t headoff = (size_t)(b * NH + h) * SS * DH;
    const float* __restrict__ Qg = g_Q + headoff;
    const float* __restrict__ Kg = g_K + headoff;
    const float* __restrict__ Vg = g_V + headoff;

    for (int qh = 0; qh < 2; qh++) {
        const int q0 = (blockIdx.x << 7) + (qh << 6);
        __syncthreads();
#pragma unroll
        for (int it = 0; it < 8; it++) {
            int idx = tid + it * 256;
            int row = idx >> 5;
            int d4  = (idx & 31) << 2;
            *(float4*)&Qs[row * QS_LD + d4] =
                *(const float4*)(Qg + (size_t)(q0 + row) * DH + d4);
        }

        const int r0 = ty * 4;
        float m_i[4], l_i[4], acc[4][8];
#pragma unroll
        for (int i = 0; i < 4; i++) {
            m_i[i] = -1e30f;
            l_i[i] = 0.0f;
#pragma unroll
            for (int j = 0; j < 8; j++) acc[i][j] = 0.0f;
        }

        for (int kv0 = 0; kv0 < SS; kv0 += 64) {
            __syncthreads();
#pragma unroll
            for (int it = 0; it < 8; it++) {
                int idx = tid + it * 256;
                int row = idx >> 5;
                int d4  = (idx & 31) << 2;
                *(float4*)&Ks[row * QS_LD + d4] =
                    *(const float4*)(Kg + (size_t)(kv0 + row) * DH + d4);
                *(float4*)&Vs[row * 128 + d4] =
                    *(const float4*)(Vg + (size_t)(kv0 + row) * DH + d4);
            }
            __syncthreads();

            float s[4][4];
#pragma unroll
            for (int i = 0; i < 4; i++)
#pragma unroll
                for (int j = 0; j < 4; j++) s[i][j] = 0.0f;

#pragma unroll 8
            for (int d = 0; d < DH; d += 4) {
                float4 q[4], k[4];
#pragma unroll
                for (int i = 0; i < 4; i++) q[i] = *(float4*)&Qs[(r0 + i) * QS_LD + d];
#pragma unroll
                for (int j = 0; j < 4; j++) k[j] = *(float4*)&Ks[(tx + 16 * j) * QS_LD + d];
#pragma unroll
                for (int i = 0; i < 4; i++)
#pragma unroll
                    for (int j = 0; j < 4; j++)
                        s[i][j] += q[i].x * k[j].x + q[i].y * k[j].y +
                                   q[i].z * k[j].z + q[i].w * k[j].w;
            }

#pragma unroll
            for (int i = 0; i < 4; i++) {
                const float* mrow = mask + (size_t)(q0 + r0 + i) * SS + kv0;
#pragma unroll
                for (int j = 0; j < 4; j++)
                    s[i][j] = s[i][j] * scale + mrow[tx + 16 * j];

                float mx = fmaxf(fmaxf(s[i][0], s[i][1]), fmaxf(s[i][2], s[i][3]));
#pragma unroll
                for (int o = 1; o < 16; o <<= 1)
                    mx = fmaxf(mx, __shfl_xor_sync(0xffffffffu, mx, o));
                float mnew = fmaxf(m_i[i], mx);

                float sum = 0.0f;
#pragma unroll
                for (int j = 0; j < 4; j++) {
                    s[i][j] = __expf(s[i][j] - mnew);
                    sum += s[i][j];
                }
#pragma unroll
                for (int o = 1; o < 16; o <<= 1)
                    sum += __shfl_xor_sync(0xffffffffu, sum, o);

                float alpha = __expf(m_i[i] - mnew);
                l_i[i] = l_i[i] * alpha + sum;
                m_i[i] = mnew;
#pragma unroll
                for (int j = 0; j < 8; j++) acc[i][j] *= alpha;
            }

#pragma unroll
            for (int j = 0; j < 4; j++)
#pragma unroll
                for (int i = 0; i < 4; i++)
                    Pt[(tx + 16 * j) * PT_LD + r0 + i] = s[i][j];
            __syncthreads();

#pragma unroll 8
            for (int c = 0; c < 64; c++) {
                float4 p  = *(float4*)&Pt[c * PT_LD + r0];
                float4 v0 = *(float4*)&Vs[c * 128 + tx * 8];
                float4 v1 = *(float4*)&Vs[c * 128 + tx * 8 + 4];
                float pa[4] = {p.x, p.y, p.z, p.w};
                float va[8] = {v0.x, v0.y, v0.z, v0.w, v1.x, v1.y, v1.z, v1.w};
#pragma unroll
                for (int i = 0; i < 4; i++)
#pragma unroll
                    for (int j = 0; j < 8; j++)
                        acc[i][j] += pa[i] * va[j];
            }
        }

#pragma unroll
        for (int i = 0; i < 4; i++) {
            float inv = 1.0f / l_i[i];
            size_t base = ((size_t)b * SS + q0 + r0 + i) * DM + h * DH + tx * 8;
            __nv_bfloat16 hh[8], ll[8];
#pragma unroll
            for (int j = 0; j < 8; j++) {
                float v = acc[i][j] * inv;
                hh[j] = __float2bfloat16(v);
                ll[j] = __float2bfloat16(v - __bfloat162float(hh[j]));
            }
            *(uint4*)&g_Ch[base] = *(uint4*)hh;
            *(uint4*)&g_Cl[base] = *(uint4*)ll;
        }
    }
#endif
}

// ---------------------------------------------------------------------------
extern "C" void kernel_launch(void* const* d_in, const int* in_sizes, int n_in,
                              void* d_out, int out_size)
{
    const float* x    = (const float*)d_in[0];
    const float* mask = (const float*)d_in[1];
    const float* wq   = (const float*)d_in[2];
    const float* bq   = (const float*)d_in[3];
    const float* wk   = (const float*)d_in[4];
    const float* bk   = (const float*)d_in[5];
    const float* wv   = (const float*)d_in[6];
    const float* bv   = (const float*)d_in[7];
    const float* wo   = (const float*)d_in[8];
    const float* bo   = (const float*)d_in[9];
    float* out = (float*)d_out;

    cudaFuncSetAttribute(tc_gemm, cudaFuncAttributeMaxDynamicSharedMemorySize, GEMM_SMEM);
    cudaFuncSetAttribute(attn_kernel, cudaFuncAttributeMaxDynamicSharedMemorySize, ATT_SMEM);

    split_x_kernel<<<(MT * DM) / (256 * 4), 256>>>(x);
    wsplit_kernel<<<dim3(64, 64, 4), 256>>>(wq, wk, wv, wo);
    mtrans_kernel<<<dim3(SS / 32, SS / 32), 256>>>(mask);

    // QKV projections (256x256 per CTA)
    tc_gemm<<<dim3(DM / 256, MT / 256, 3), 256, GEMM_SMEM>>>(bq, bk, bv, nullptr, 0, 1);

    // attention
    const float scale = 0.08838834764831845f;  // 1/sqrt(128)
    attn_kernel<<<dim3(SS / 128, NH, BB), 256, ATT_SMEM>>>(mask, scale);

    // output projection (256x256 per CTA)
    tc_gemm<<<dim3(DM / 256, MT / 256, 1), 256, GEMM_SMEM>>>(bo, bo, bo, out, 3, 0);
}